// round 2
// baseline (speedup 1.0000x reference)
#include <cuda_runtime.h>
#include <math.h>

#define BN_EPS 1e-5f

// Problem constants (fixed by the reference setup)
#define B_   2
#define C_   512
#define HW_  6400
#define CK_  256
#define CV_  256
#define CO_  512

// ---------------------------------------------------------------------------
// Scratch (device globals: allocation-free per harness rules)
// ---------------------------------------------------------------------------
__device__ float g_k[B_ * CK_ * HW_];            // 13.1 MB  key (=query^T) after BN+ReLU
__device__ float g_v[B_ * CV_ * HW_];            // 13.1 MB  value
__device__ float g_sim[B_ * HW_ * HW_];          // 327.7 MB attention matrix
__device__ float g_ctx[B_ * CV_ * HW_];          // 13.1 MB  context

// ---------------------------------------------------------------------------
// Kernel 1: k = relu(BN(Wk x + bk)),  v = Wv x + bv
// GEMM: out[m,n] = sum_c W[m,c] * X[c,n];  M=256, K=512, N=6400
// grid (100, 4, 4)  z = batch*2 + (0:k, 1:v)
// ---------------------------------------------------------------------------
__global__ void __launch_bounds__(256) kv_kernel(
    const float* __restrict__ x,
    const float* __restrict__ wk, const float* __restrict__ bk,
    const float* __restrict__ gamma, const float* __restrict__ beta,
    const float* __restrict__ rmean, const float* __restrict__ rvar,
    const float* __restrict__ wv, const float* __restrict__ bv)
{
    const int n0 = blockIdx.x * 64;
    const int m0 = blockIdx.y * 64;
    const int b  = blockIdx.z >> 1;
    const int isV = blockIdx.z & 1;
    const float* W  = isV ? wv : wk;
    const float* Xb = x + (size_t)b * C_ * HW_;

    __shared__ float As[16][68];  // As[k][m]
    __shared__ float Bs[16][68];  // Bs[k][n]

    const int tid = threadIdx.x;
    const int tx = tid & 15, ty = tid >> 4;

    float acc[4][4] = {};

    for (int k0 = 0; k0 < C_; k0 += 16) {
        {   // A tile [64 m][16 k] -> transposed
            int m  = tid >> 2;
            int kg = (tid & 3) * 4;
            float4 f = *(const float4*)&W[(size_t)(m0 + m) * C_ + k0 + kg];
            As[kg + 0][m] = f.x; As[kg + 1][m] = f.y;
            As[kg + 2][m] = f.z; As[kg + 3][m] = f.w;
        }
        {   // B tile [16 k][64 n] direct
            int kk = tid >> 4;
            int ng = (tid & 15) * 4;
            *(float4*)&Bs[kk][ng] =
                *(const float4*)&Xb[(size_t)(k0 + kk) * HW_ + n0 + ng];
        }
        __syncthreads();
        #pragma unroll
        for (int kk = 0; kk < 16; kk++) {
            float4 a  = *(const float4*)&As[kk][ty * 4];
            float4 bb = *(const float4*)&Bs[kk][tx * 4];
            float av[4] = {a.x, a.y, a.z, a.w};
            float bv4[4] = {bb.x, bb.y, bb.z, bb.w};
            #pragma unroll
            for (int i = 0; i < 4; i++)
                #pragma unroll
                for (int j = 0; j < 4; j++)
                    acc[i][j] = fmaf(av[i], bv4[j], acc[i][j]);
        }
        __syncthreads();
    }

    float* out = (isV ? g_v : g_k) + (size_t)b * CK_ * HW_;
    #pragma unroll
    for (int i = 0; i < 4; i++) {
        int m = m0 + ty * 4 + i;
        float bias = isV ? bv[m] : bk[m];
        float sc = 0.f, mu = 0.f, be = 0.f;
        if (!isV) {
            sc = gamma[m] / sqrtf(rvar[m] + BN_EPS);
            mu = rmean[m];
            be = beta[m];
        }
        float vals[4];
        #pragma unroll
        for (int j = 0; j < 4; j++) {
            float t = acc[i][j] + bias;
            if (!isV) {
                t = (t - mu) * sc + be;
                t = fmaxf(t, 0.f);
            }
            vals[j] = t;
        }
        *(float4*)&out[(size_t)m * HW_ + n0 + tx * 4] =
            make_float4(vals[0], vals[1], vals[2], vals[3]);
    }
}

// ---------------------------------------------------------------------------
// Kernel 2: sim[n_q, n_k] = (1/16) * sum_c K[c, n_q] * K[c, n_k]
// grid (100, 100, 2)
// ---------------------------------------------------------------------------
__global__ void __launch_bounds__(256) sim_kernel()
{
    const int n0 = blockIdx.x * 64;   // key col
    const int m0 = blockIdx.y * 64;   // query row
    const int b  = blockIdx.z;
    const float* K = g_k + (size_t)b * CK_ * HW_;

    __shared__ float As[16][68];  // As[c][m]  (queries)
    __shared__ float Bs[16][68];  // Bs[c][n]  (keys)

    const int tid = threadIdx.x;
    const int tx = tid & 15, ty = tid >> 4;

    float acc[4][4] = {};

    for (int c0 = 0; c0 < CK_; c0 += 16) {
        int kk = tid >> 4;
        int g  = (tid & 15) * 4;
        *(float4*)&As[kk][g] = *(const float4*)&K[(size_t)(c0 + kk) * HW_ + m0 + g];
        *(float4*)&Bs[kk][g] = *(const float4*)&K[(size_t)(c0 + kk) * HW_ + n0 + g];
        __syncthreads();
        #pragma unroll
        for (int c = 0; c < 16; c++) {
            float4 a  = *(const float4*)&As[c][ty * 4];
            float4 bb = *(const float4*)&Bs[c][tx * 4];
            float av[4] = {a.x, a.y, a.z, a.w};
            float bv4[4] = {bb.x, bb.y, bb.z, bb.w};
            #pragma unroll
            for (int i = 0; i < 4; i++)
                #pragma unroll
                for (int j = 0; j < 4; j++)
                    acc[i][j] = fmaf(av[i], bv4[j], acc[i][j]);
        }
        __syncthreads();
    }

    float* S = g_sim + (size_t)b * HW_ * HW_;
    const float scale = 0.0625f;   // 256^-0.5
    #pragma unroll
    for (int i = 0; i < 4; i++) {
        int m = m0 + ty * 4 + i;
        *(float4*)&S[(size_t)m * HW_ + n0 + tx * 4] =
            make_float4(acc[i][0] * scale, acc[i][1] * scale,
                        acc[i][2] * scale, acc[i][3] * scale);
    }
}

// ---------------------------------------------------------------------------
// Kernel 3: row softmax over the 6400-wide contiguous axis (in place)
// grid (12800), 256 threads
// ---------------------------------------------------------------------------
__global__ void __launch_bounds__(256) softmax_kernel()
{
    const size_t row = blockIdx.x;
    float* S = g_sim + row * HW_;
    __shared__ float red[256];
    const int tid = threadIdx.x;

    // pass 1: max
    float mx = -1e30f;
    for (int i = tid; i < HW_ / 4; i += 256) {
        float4 f = *(const float4*)&S[i * 4];
        mx = fmaxf(mx, fmaxf(fmaxf(f.x, f.y), fmaxf(f.z, f.w)));
    }
    red[tid] = mx;
    __syncthreads();
    for (int s = 128; s > 0; s >>= 1) {
        if (tid < s) red[tid] = fmaxf(red[tid], red[tid + s]);
        __syncthreads();
    }
    mx = red[0];
    __syncthreads();

    // pass 2: exp + sum
    float sum = 0.f;
    for (int i = tid; i < HW_ / 4; i += 256) {
        float4 f = *(const float4*)&S[i * 4];
        f.x = __expf(f.x - mx); f.y = __expf(f.y - mx);
        f.z = __expf(f.z - mx); f.w = __expf(f.w - mx);
        *(float4*)&S[i * 4] = f;
        sum += f.x + f.y + f.z + f.w;
    }
    red[tid] = sum;
    __syncthreads();
    for (int s = 128; s > 0; s >>= 1) {
        if (tid < s) red[tid] += red[tid + s];
        __syncthreads();
    }
    const float inv = 1.f / red[0];

    // pass 3: normalize
    for (int i = tid; i < HW_ / 4; i += 256) {
        float4 f = *(const float4*)&S[i * 4];
        f.x *= inv; f.y *= inv; f.z *= inv; f.w *= inv;
        *(float4*)&S[i * 4] = f;
    }
}

// ---------------------------------------------------------------------------
// Kernel 4: ctx[v, n] = sum_m sim[n, m] * V[v, m]
// M=v(256), N=n(6400), K=m(6400);  grid (100, 4, 2)
// ---------------------------------------------------------------------------
__global__ void __launch_bounds__(256) ctx_kernel()
{
    const int n0 = blockIdx.x * 64;
    const int v0 = blockIdx.y * 64;
    const int b  = blockIdx.z;
    const float* V = g_v + (size_t)b * CV_ * HW_;
    const float* P = g_sim + (size_t)b * HW_ * HW_;

    __shared__ float As[16][68];  // As[m][v]
    __shared__ float Bs[16][68];  // Bs[m][n]

    const int tid = threadIdx.x;
    const int tx = tid & 15, ty = tid >> 4;

    float acc[4][4] = {};

    for (int m0 = 0; m0 < HW_; m0 += 16) {
        {   // A tile: V[v0+vv][m0+mm], transposed store
            int vv = tid >> 2;
            int mg = (tid & 3) * 4;
            float4 f = *(const float4*)&V[(size_t)(v0 + vv) * HW_ + m0 + mg];
            As[mg + 0][vv] = f.x; As[mg + 1][vv] = f.y;
            As[mg + 2][vv] = f.z; As[mg + 3][vv] = f.w;
        }
        {   // B tile: P[n0+nn][m0+mm], transposed store
            int nn = tid >> 2;
            int mg = (tid & 3) * 4;
            float4 f = *(const float4*)&P[(size_t)(n0 + nn) * HW_ + m0 + mg];
            Bs[mg + 0][nn] = f.x; Bs[mg + 1][nn] = f.y;
            Bs[mg + 2][nn] = f.z; Bs[mg + 3][nn] = f.w;
        }
        __syncthreads();
        #pragma unroll
        for (int kk = 0; kk < 16; kk++) {
            float4 a  = *(const float4*)&As[kk][ty * 4];
            float4 bb = *(const float4*)&Bs[kk][tx * 4];
            float av[4] = {a.x, a.y, a.z, a.w};
            float bv4[4] = {bb.x, bb.y, bb.z, bb.w};
            #pragma unroll
            for (int i = 0; i < 4; i++)
                #pragma unroll
                for (int j = 0; j < 4; j++)
                    acc[i][j] = fmaf(av[i], bv4[j], acc[i][j]);
        }
        __syncthreads();
    }

    float* ctx = g_ctx + (size_t)b * CV_ * HW_;
    #pragma unroll
    for (int i = 0; i < 4; i++) {
        int v = v0 + ty * 4 + i;
        *(float4*)&ctx[(size_t)v * HW_ + n0 + tx * 4] =
            make_float4(acc[i][0], acc[i][1], acc[i][2], acc[i][3]);
    }
}

// ---------------------------------------------------------------------------
// Kernel 5: out[o, n] = sum_v wW[o, v] * ctx[v, n] + bW[o]
// M=512, K=256, N=6400;  grid (100, 8, 2)
// ---------------------------------------------------------------------------
__global__ void __launch_bounds__(256) out_kernel(
    const float* __restrict__ wW, const float* __restrict__ bW,
    float* __restrict__ out)
{
    const int n0 = blockIdx.x * 64;
    const int o0 = blockIdx.y * 64;
    const int b  = blockIdx.z;
    const float* Cx = g_ctx + (size_t)b * CV_ * HW_;

    __shared__ float As[16][68];  // As[v][o]
    __shared__ float Bs[16][68];  // Bs[v][n]

    const int tid = threadIdx.x;
    const int tx = tid & 15, ty = tid >> 4;

    float acc[4][4] = {};

    for (int k0 = 0; k0 < CV_; k0 += 16) {
        {   // A tile: wW[o0+m][k0+kg], transposed store
            int m  = tid >> 2;
            int kg = (tid & 3) * 4;
            float4 f = *(const float4*)&wW[(size_t)(o0 + m) * CV_ + k0 + kg];
            As[kg + 0][m] = f.x; As[kg + 1][m] = f.y;
            As[kg + 2][m] = f.z; As[kg + 3][m] = f.w;
        }
        {   // B tile direct
            int kk = tid >> 4;
            int ng = (tid & 15) * 4;
            *(float4*)&Bs[kk][ng] =
                *(const float4*)&Cx[(size_t)(k0 + kk) * HW_ + n0 + ng];
        }
        __syncthreads();
        #pragma unroll
        for (int kk = 0; kk < 16; kk++) {
            float4 a  = *(const float4*)&As[kk][ty * 4];
            float4 bb = *(const float4*)&Bs[kk][tx * 4];
            float av[4] = {a.x, a.y, a.z, a.w};
            float bv4[4] = {bb.x, bb.y, bb.z, bb.w};
            #pragma unroll
            for (int i = 0; i < 4; i++)
                #pragma unroll
                for (int j = 0; j < 4; j++)
                    acc[i][j] = fmaf(av[i], bv4[j], acc[i][j]);
        }
        __syncthreads();
    }

    #pragma unroll
    for (int i = 0; i < 4; i++) {
        int o = o0 + ty * 4 + i;
        float bias = bW[o];
        *(float4*)&out[(size_t)b * CO_ * HW_ + (size_t)o * HW_ + n0 + tx * 4] =
            make_float4(acc[i][0] + bias, acc[i][1] + bias,
                        acc[i][2] + bias, acc[i][3] + bias);
    }
}

// ---------------------------------------------------------------------------
// Launch
// ---------------------------------------------------------------------------
extern "C" void kernel_launch(void* const* d_in, const int* in_sizes, int n_in,
                              void* d_out, int out_size)
{
    const float* x     = (const float*)d_in[0];
    const float* wk    = (const float*)d_in[1];
    const float* bk    = (const float*)d_in[2];
    const float* gamma = (const float*)d_in[3];
    const float* beta  = (const float*)d_in[4];
    const float* rmean = (const float*)d_in[5];
    const float* rvar  = (const float*)d_in[6];
    const float* wv    = (const float*)d_in[7];
    const float* bv    = (const float*)d_in[8];
    const float* wW    = (const float*)d_in[9];
    const float* bW    = (const float*)d_in[10];
    float* out = (float*)d_out;

    dim3 blk(256);
    kv_kernel<<<dim3(100, 4, 4), blk>>>(x, wk, bk, gamma, beta, rmean, rvar, wv, bv);
    sim_kernel<<<dim3(100, 100, 2), blk>>>();
    softmax_kernel<<<dim3(12800, 1, 1), blk>>>();
    ctx_kernel<<<dim3(100, 4, 2), blk>>>();
    out_kernel<<<dim3(100, 8, 2), blk>>>(wW, bW, out);
}

// round 3
// speedup vs baseline: 1.9568x; 1.9568x over previous
#include <cuda_runtime.h>
#include <math.h>
#include <stdint.h>

#define BN_EPS 1e-5f

// Problem constants
#define B_   2
#define C_   512
#define HW_  6400
#define CK_  256
#define CV_  256
#define CO_  512

// ---------------------------------------------------------------------------
// Scratch (device globals)
// ---------------------------------------------------------------------------
__device__ float g_kt[(size_t)B_ * HW_ * CK_];    // 13.1 MB  K^T: [pixel][channel]
__device__ float g_v [(size_t)B_ * CV_ * HW_];    // 13.1 MB  V:   [channel][pixel]
__device__ float g_sim[(size_t)B_ * HW_ * HW_];   // 327.7 MB attention (logits -> probs in place)
__device__ float g_ctx[(size_t)B_ * CV_ * HW_];   // 13.1 MB  context [channel][pixel]

// ---------------------------------------------------------------------------
// TF32 mma helpers
// ---------------------------------------------------------------------------
__device__ __forceinline__ uint32_t f2tf(float f) {
    uint32_t u;
    asm("cvt.rna.tf32.f32 %0, %1;" : "=r"(u) : "f"(f));
    return u;
}

__device__ __forceinline__ void mma_tf32(float* c, const uint32_t* a, const uint32_t* b) {
    asm volatile(
        "mma.sync.aligned.m16n8k8.row.col.f32.tf32.tf32.f32 "
        "{%0,%1,%2,%3}, {%4,%5,%6,%7}, {%8,%9}, {%0,%1,%2,%3};"
        : "+f"(c[0]), "+f"(c[1]), "+f"(c[2]), "+f"(c[3])
        : "r"(a[0]), "r"(a[1]), "r"(a[2]), "r"(a[3]), "r"(b[0]), "r"(b[1]));
}

// ---------------------------------------------------------------------------
// Shared TF32 GEMM body: C[m][n] = scale * sum_k A[m][k] * B[n][k]
// Block tile 128x128, 256 threads = 8 warps (4 along M x 2 along N), warp 32x64.
// A rows are the M dim, B rows are the N dim; k contiguous in both.
// ---------------------------------------------------------------------------
__device__ __forceinline__ void mma_gemm_body(
    const float* __restrict__ A, const float* __restrict__ B,
    float* __restrict__ C, int K, int lda, int ldb, int ldc, float scale)
{
    __shared__ uint32_t As[128][36];
    __shared__ uint32_t Bs[128][36];

    const int tid  = threadIdx.x;
    const int lane = tid & 31;
    const int wid  = tid >> 5;
    const int warpM0 = (wid & 3) * 32;
    const int warpN0 = (wid >> 2) * 64;
    const int t4 = lane >> 2;     // 0..7
    const int tm = lane & 3;      // 0..3
    const int m0 = blockIdx.y * 128;
    const int n0 = blockIdx.x * 128;

    const int lr = tid >> 1;          // 0..127 load row
    const int lc = (tid & 1) * 16;    // load col base

    float acc[2][8][4] = {};

    for (int k0 = 0; k0 < K; k0 += 32) {
        const float* Ap = A + (size_t)(m0 + lr) * lda + k0 + lc;
        const float* Bp = B + (size_t)(n0 + lr) * ldb + k0 + lc;
        #pragma unroll
        for (int i = 0; i < 4; i++) {
            float4 fa = *(const float4*)(Ap + i * 4);
            float4 fb = *(const float4*)(Bp + i * 4);
            uint4 ua = make_uint4(f2tf(fa.x), f2tf(fa.y), f2tf(fa.z), f2tf(fa.w));
            uint4 ub = make_uint4(f2tf(fb.x), f2tf(fb.y), f2tf(fb.z), f2tf(fb.w));
            *(uint4*)&As[lr][lc + i * 4] = ua;
            *(uint4*)&Bs[lr][lc + i * 4] = ub;
        }
        __syncthreads();

        #pragma unroll
        for (int s = 0; s < 4; s++) {
            uint32_t a[2][4], b[8][2];
            #pragma unroll
            for (int i = 0; i < 2; i++) {
                int r = warpM0 + i * 16 + t4;
                a[i][0] = As[r][s * 8 + tm];
                a[i][1] = As[r + 8][s * 8 + tm];
                a[i][2] = As[r][s * 8 + tm + 4];
                a[i][3] = As[r + 8][s * 8 + tm + 4];
            }
            #pragma unroll
            for (int j = 0; j < 8; j++) {
                int r = warpN0 + j * 8 + t4;
                b[j][0] = Bs[r][s * 8 + tm];
                b[j][1] = Bs[r][s * 8 + tm + 4];
            }
            #pragma unroll
            for (int i = 0; i < 2; i++)
                #pragma unroll
                for (int j = 0; j < 8; j++)
                    mma_tf32(acc[i][j], a[i], b[j]);
        }
        __syncthreads();
    }

    #pragma unroll
    for (int i = 0; i < 2; i++) {
        int r1 = m0 + warpM0 + i * 16 + t4;
        int r2 = r1 + 8;
        #pragma unroll
        for (int j = 0; j < 8; j++) {
            int cg = n0 + warpN0 + j * 8 + tm * 2;
            float2 lo = make_float2(acc[i][j][0] * scale, acc[i][j][1] * scale);
            float2 hi = make_float2(acc[i][j][2] * scale, acc[i][j][3] * scale);
            *(float2*)&C[(size_t)r1 * ldc + cg] = lo;
            *(float2*)&C[(size_t)r2 * ldc + cg] = hi;
        }
    }
}

// sim[m][n] = (1/16) * K^T[m][:] . K^T[n][:]      grid (50, 50, 2)
__global__ void __launch_bounds__(256) sim_mma()
{
    const int b = blockIdx.z;
    mma_gemm_body(g_kt + (size_t)b * HW_ * CK_,
                  g_kt + (size_t)b * HW_ * CK_,
                  g_sim + (size_t)b * HW_ * HW_,
                  CK_, CK_, CK_, HW_, 0.0625f);
}

// ctx[v][n] = V[v][:] . P[n][:]                   grid (50, 2, 2)
__global__ void __launch_bounds__(256) ctx_mma()
{
    const int b = blockIdx.z;
    mma_gemm_body(g_v + (size_t)b * CV_ * HW_,
                  g_sim + (size_t)b * HW_ * HW_,
                  g_ctx + (size_t)b * CV_ * HW_,
                  HW_, HW_, HW_, HW_, 1.0f);
}

// ---------------------------------------------------------------------------
// Kernel 1: k = relu(BN(Wk x + bk)) written transposed to g_kt,
//           v = Wv x + bv written to g_v.
// grid (100, 4, 4)  z = batch*2 + (0:k, 1:v)
// ---------------------------------------------------------------------------
__global__ void __launch_bounds__(256) kv_kernel(
    const float* __restrict__ x,
    const float* __restrict__ wk, const float* __restrict__ bk,
    const float* __restrict__ gamma, const float* __restrict__ beta,
    const float* __restrict__ rmean, const float* __restrict__ rvar,
    const float* __restrict__ wv, const float* __restrict__ bv)
{
    const int n0 = blockIdx.x * 64;
    const int m0 = blockIdx.y * 64;
    const int b  = blockIdx.z >> 1;
    const int isV = blockIdx.z & 1;
    const float* W  = isV ? wv : wk;
    const float* Xb = x + (size_t)b * C_ * HW_;

    __shared__ float As[16][68];
    __shared__ float Bs[16][68];

    const int tid = threadIdx.x;
    const int tx = tid & 15, ty = tid >> 4;

    float acc[4][4] = {};

    for (int k0 = 0; k0 < C_; k0 += 16) {
        {
            int m  = tid >> 2;
            int kg = (tid & 3) * 4;
            float4 f = *(const float4*)&W[(size_t)(m0 + m) * C_ + k0 + kg];
            As[kg + 0][m] = f.x; As[kg + 1][m] = f.y;
            As[kg + 2][m] = f.z; As[kg + 3][m] = f.w;
        }
        {
            int kk = tid >> 4;
            int ng = (tid & 15) * 4;
            *(float4*)&Bs[kk][ng] =
                *(const float4*)&Xb[(size_t)(k0 + kk) * HW_ + n0 + ng];
        }
        __syncthreads();
        #pragma unroll
        for (int kk = 0; kk < 16; kk++) {
            float4 a  = *(const float4*)&As[kk][ty * 4];
            float4 bb = *(const float4*)&Bs[kk][tx * 4];
            float av[4] = {a.x, a.y, a.z, a.w};
            float bv4[4] = {bb.x, bb.y, bb.z, bb.w};
            #pragma unroll
            for (int i = 0; i < 4; i++)
                #pragma unroll
                for (int j = 0; j < 4; j++)
                    acc[i][j] = fmaf(av[i], bv4[j], acc[i][j]);
        }
        __syncthreads();
    }

    if (isV) {
        float* out = g_v + (size_t)b * CV_ * HW_;
        #pragma unroll
        for (int i = 0; i < 4; i++) {
            int m = m0 + ty * 4 + i;
            float bias = bv[m];
            *(float4*)&out[(size_t)m * HW_ + n0 + tx * 4] =
                make_float4(acc[i][0] + bias, acc[i][1] + bias,
                            acc[i][2] + bias, acc[i][3] + bias);
        }
    } else {
        float* kt = g_kt + (size_t)b * HW_ * CK_;
        #pragma unroll
        for (int i = 0; i < 4; i++) {
            int m = m0 + ty * 4 + i;
            float bias = bk[m];
            float sc = gamma[m] / sqrtf(rvar[m] + BN_EPS);
            float mu = rmean[m];
            float be = beta[m];
            #pragma unroll
            for (int j = 0; j < 4; j++) {
                float t = acc[i][j] + bias;
                t = (t - mu) * sc + be;
                t = fmaxf(t, 0.f);
                kt[(size_t)(n0 + tx * 4 + j) * CK_ + m] = t;   // transposed
            }
        }
    }
}

// ---------------------------------------------------------------------------
// Kernel 3: online row softmax (2 passes), normalized fp32 written in place.
// grid (12800), 256 threads
// ---------------------------------------------------------------------------
__global__ void __launch_bounds__(256) softmax_kernel()
{
    const size_t row = blockIdx.x;
    float* S = g_sim + row * HW_;
    __shared__ float rm[256], rs[256];
    const int tid = threadIdx.x;

    // pass 1: online max + sum
    float m = -1e30f, s = 0.f;
    for (int i = tid; i < HW_ / 4; i += 256) {
        float4 f = *(const float4*)&S[i * 4];
        float vmax = fmaxf(fmaxf(f.x, f.y), fmaxf(f.z, f.w));
        if (vmax > m) { s *= __expf(m - vmax); m = vmax; }
        s += __expf(f.x - m) + __expf(f.y - m) + __expf(f.z - m) + __expf(f.w - m);
    }
    rm[tid] = m; rs[tid] = s;
    __syncthreads();
    for (int st = 128; st > 0; st >>= 1) {
        if (tid < st) {
            float m1 = rm[tid], s1 = rs[tid];
            float m2 = rm[tid + st], s2 = rs[tid + st];
            float M = fmaxf(m1, m2);
            rm[tid] = M;
            rs[tid] = s1 * __expf(m1 - M) + s2 * __expf(m2 - M);
        }
        __syncthreads();
    }
    const float M = rm[0];
    const float inv = 1.f / rs[0];

    // pass 2: normalize in place
    for (int i = tid; i < HW_ / 4; i += 256) {
        float4 f = *(const float4*)&S[i * 4];
        f.x = __expf(f.x - M) * inv;
        f.y = __expf(f.y - M) * inv;
        f.z = __expf(f.z - M) * inv;
        f.w = __expf(f.w - M) * inv;
        *(float4*)&S[i * 4] = f;
    }
}

// ---------------------------------------------------------------------------
// Kernel 5: out[o, n] = sum_v wW[o, v] * ctx[v, n] + bW[o]
// grid (100, 8, 2)
// ---------------------------------------------------------------------------
__global__ void __launch_bounds__(256) out_kernel(
    const float* __restrict__ wW, const float* __restrict__ bW,
    float* __restrict__ out)
{
    const int n0 = blockIdx.x * 64;
    const int o0 = blockIdx.y * 64;
    const int b  = blockIdx.z;
    const float* Cx = g_ctx + (size_t)b * CV_ * HW_;

    __shared__ float As[16][68];
    __shared__ float Bs[16][68];

    const int tid = threadIdx.x;
    const int tx = tid & 15, ty = tid >> 4;

    float acc[4][4] = {};

    for (int k0 = 0; k0 < CV_; k0 += 16) {
        {
            int m  = tid >> 2;
            int kg = (tid & 3) * 4;
            float4 f = *(const float4*)&wW[(size_t)(o0 + m) * CV_ + k0 + kg];
            As[kg + 0][m] = f.x; As[kg + 1][m] = f.y;
            As[kg + 2][m] = f.z; As[kg + 3][m] = f.w;
        }
        {
            int kk = tid >> 4;
            int ng = (tid & 15) * 4;
            *(float4*)&Bs[kk][ng] =
                *(const float4*)&Cx[(size_t)(k0 + kk) * HW_ + n0 + ng];
        }
        __syncthreads();
        #pragma unroll
        for (int kk = 0; kk < 16; kk++) {
            float4 a  = *(const float4*)&As[kk][ty * 4];
            float4 bb = *(const float4*)&Bs[kk][tx * 4];
            float av[4] = {a.x, a.y, a.z, a.w};
            float bv4[4] = {bb.x, bb.y, bb.z, bb.w};
            #pragma unroll
            for (int i = 0; i < 4; i++)
                #pragma unroll
                for (int j = 0; j < 4; j++)
                    acc[i][j] = fmaf(av[i], bv4[j], acc[i][j]);
        }
        __syncthreads();
    }

    #pragma unroll
    for (int i = 0; i < 4; i++) {
        int o = o0 + ty * 4 + i;
        float bias = bW[o];
        *(float4*)&out[(size_t)b * CO_ * HW_ + (size_t)o * HW_ + n0 + tx * 4] =
            make_float4(acc[i][0] + bias, acc[i][1] + bias,
                        acc[i][2] + bias, acc[i][3] + bias);
    }
}

// ---------------------------------------------------------------------------
// Launch
// ---------------------------------------------------------------------------
extern "C" void kernel_launch(void* const* d_in, const int* in_sizes, int n_in,
                              void* d_out, int out_size)
{
    const float* x     = (const float*)d_in[0];
    const float* wk    = (const float*)d_in[1];
    const float* bk    = (const float*)d_in[2];
    const float* gamma = (const float*)d_in[3];
    const float* beta  = (const float*)d_in[4];
    const float* rmean = (const float*)d_in[5];
    const float* rvar  = (const float*)d_in[6];
    const float* wv    = (const float*)d_in[7];
    const float* bv    = (const float*)d_in[8];
    const float* wW    = (const float*)d_in[9];
    const float* bW    = (const float*)d_in[10];
    float* out = (float*)d_out;

    dim3 blk(256);
    kv_kernel<<<dim3(100, 4, 4), blk>>>(x, wk, bk, gamma, beta, rmean, rvar, wv, bv);
    sim_mma<<<dim3(50, 50, 2), blk>>>();
    softmax_kernel<<<dim3(12800, 1, 1), blk>>>();
    ctx_mma<<<dim3(50, 2, 2), blk>>>();
    out_kernel<<<dim3(100, 8, 2), blk>>>(wW, bW, out);
}

// round 5
// speedup vs baseline: 2.2739x; 1.1621x over previous
#include <cuda_runtime.h>
#include <math.h>
#include <stdint.h>

#define BN_EPS 1e-5f

// Problem constants
#define B_   2
#define C_   512
#define HW_  6400
#define CK_  256
#define CV_  256
#define CO_  512
#define NSPLIT 4
#define KSPLIT (HW_ / NSPLIT)   // 1600

// ---------------------------------------------------------------------------
// Scratch (device globals)
// ---------------------------------------------------------------------------
__device__ float g_kt  [(size_t)B_ * HW_ * CK_];           // K^T: [pixel][channel]
__device__ float g_v   [(size_t)B_ * CV_ * HW_];           // V:   [channel][pixel]
__device__ float g_sim [(size_t)B_ * HW_ * HW_];           // attention probs
__device__ float g_ctxp[(size_t)B_ * NSPLIT * HW_ * CV_];  // ctx partials [b*4+s][n][v]
__device__ float g_ctx [(size_t)B_ * HW_ * CV_];           // ctx^T: [n][v]

// ---------------------------------------------------------------------------
// TF32 mma helpers
// ---------------------------------------------------------------------------
__device__ __forceinline__ uint32_t f2tf(float f) {
    uint32_t u;
    asm("cvt.rna.tf32.f32 %0, %1;" : "=r"(u) : "f"(f));
    return u;
}

__device__ __forceinline__ void mma_tf32(float* c, const uint32_t* a, const uint32_t* b) {
    asm volatile(
        "mma.sync.aligned.m16n8k8.row.col.f32.tf32.tf32.f32 "
        "{%0,%1,%2,%3}, {%4,%5,%6,%7}, {%8,%9}, {%0,%1,%2,%3};"
        : "+f"(c[0]), "+f"(c[1]), "+f"(c[2]), "+f"(c[3])
        : "r"(a[0]), "r"(a[1]), "r"(a[2]), "r"(a[3]), "r"(b[0]), "r"(b[1]));
}

// ---------------------------------------------------------------------------
// Shared TF32 GEMM body: C[m][n] = scale * sum_{k in [kb,ke)} A[m][k]*B[n][k] (+bias[m])
// Block tile 128x128, 256 threads = 8 warps (4 along M x 2 along N).
// Register-prefetch double buffering on the global loads.
// ---------------------------------------------------------------------------
__device__ __forceinline__ void mma_gemm_body(
    const float* __restrict__ A, const float* __restrict__ B,
    float* __restrict__ C, int kb, int ke,
    int lda, int ldb, int ldc, float scale, const float* __restrict__ bias,
    int m0, int n0)
{
    __shared__ uint32_t As[128][36];
    __shared__ uint32_t Bs[128][36];

    const int tid  = threadIdx.x;
    const int lane = tid & 31;
    const int wid  = tid >> 5;
    const int warpM0 = (wid & 3) * 32;
    const int warpN0 = (wid >> 2) * 64;
    const int t4 = lane >> 2;
    const int tm = lane & 3;

    const int lr = tid >> 1;
    const int lc = (tid & 1) * 16;

    const float* Abase = A + (size_t)(m0 + lr) * lda + lc;
    const float* Bbase = B + (size_t)(n0 + lr) * ldb + lc;

    float acc[2][8][4] = {};
    float4 ra[4], rb[4];

    // prefetch first chunk
    #pragma unroll
    for (int i = 0; i < 4; i++) {
        ra[i] = *(const float4*)(Abase + kb + i * 4);
        rb[i] = *(const float4*)(Bbase + kb + i * 4);
    }

    for (int k0 = kb; k0 < ke; k0 += 32) {
        // commit prefetched regs to smem (with tf32 rounding)
        #pragma unroll
        for (int i = 0; i < 4; i++) {
            *(uint4*)&As[lr][lc + i * 4] =
                make_uint4(f2tf(ra[i].x), f2tf(ra[i].y), f2tf(ra[i].z), f2tf(ra[i].w));
            *(uint4*)&Bs[lr][lc + i * 4] =
                make_uint4(f2tf(rb[i].x), f2tf(rb[i].y), f2tf(rb[i].z), f2tf(rb[i].w));
        }
        __syncthreads();

        // issue next chunk's LDGs early (overlap with mma)
        if (k0 + 32 < ke) {
            #pragma unroll
            for (int i = 0; i < 4; i++) {
                ra[i] = *(const float4*)(Abase + k0 + 32 + i * 4);
                rb[i] = *(const float4*)(Bbase + k0 + 32 + i * 4);
            }
        }

        #pragma unroll
        for (int s = 0; s < 4; s++) {
            uint32_t a[2][4], b[8][2];
            #pragma unroll
            for (int i = 0; i < 2; i++) {
                int r = warpM0 + i * 16 + t4;
                a[i][0] = As[r][s * 8 + tm];
                a[i][1] = As[r + 8][s * 8 + tm];
                a[i][2] = As[r][s * 8 + tm + 4];
                a[i][3] = As[r + 8][s * 8 + tm + 4];
            }
            #pragma unroll
            for (int j = 0; j < 8; j++) {
                int r = warpN0 + j * 8 + t4;
                b[j][0] = Bs[r][s * 8 + tm];
                b[j][1] = Bs[r][s * 8 + tm + 4];
            }
            #pragma unroll
            for (int i = 0; i < 2; i++)
                #pragma unroll
                for (int j = 0; j < 8; j++)
                    mma_tf32(acc[i][j], a[i], b[j]);
        }
        __syncthreads();
    }

    #pragma unroll
    for (int i = 0; i < 2; i++) {
        int r1 = m0 + warpM0 + i * 16 + t4;
        int r2 = r1 + 8;
        float b1 = bias ? bias[r1] : 0.f;
        float b2 = bias ? bias[r2] : 0.f;
        #pragma unroll
        for (int j = 0; j < 8; j++) {
            int cg = n0 + warpN0 + j * 8 + tm * 2;
            *(float2*)&C[(size_t)r1 * ldc + cg] =
                make_float2(acc[i][j][0] * scale + b1, acc[i][j][1] * scale + b1);
            *(float2*)&C[(size_t)r2 * ldc + cg] =
                make_float2(acc[i][j][2] * scale + b2, acc[i][j][3] * scale + b2);
        }
    }
}

// sim[m][n] = (1/16) * Kt[m][:] . Kt[n][:]       grid (50, 50, 2)
__global__ void __launch_bounds__(256) sim_mma()
{
    const int b = blockIdx.z;
    mma_gemm_body(g_kt + (size_t)b * HW_ * CK_,
                  g_kt + (size_t)b * HW_ * CK_,
                  g_sim + (size_t)b * HW_ * HW_,
                  0, CK_, CK_, CK_, HW_, 0.0625f, nullptr,
                  blockIdx.y * 128, blockIdx.x * 128);
}

// ctx_t[n][v] partial = sum_{m in split} P[n][m] * V[v][m]     grid (2, 50, 8)
__global__ void __launch_bounds__(256) ctx_mma()
{
    const int b = blockIdx.z >> 2;
    const int sp = blockIdx.z & 3;
    mma_gemm_body(g_sim + (size_t)b * HW_ * HW_,
                  g_v + (size_t)b * CV_ * HW_,
                  g_ctxp + (size_t)(b * NSPLIT + sp) * HW_ * CV_,
                  sp * KSPLIT, (sp + 1) * KSPLIT,
                  HW_, HW_, CV_, 1.0f, nullptr,
                  blockIdx.y * 128, blockIdx.x * 128);
}

// g_ctx = sum of 4 partials           grid (3200), 256 threads
__global__ void __launch_bounds__(256) reduce_ctx()
{
    const size_t f = (size_t)blockIdx.x * 256 + threadIdx.x;  // float4 index
    const size_t per_b = (size_t)HW_ * CV_;                   // floats per batch
    const size_t g = f * 4;
    const size_t b = g / per_b;
    const size_t e = g % per_b;
    const float4* p0 = (const float4*)&g_ctxp[(b * NSPLIT + 0) * per_b + e];
    const float4* p1 = (const float4*)&g_ctxp[(b * NSPLIT + 1) * per_b + e];
    const float4* p2 = (const float4*)&g_ctxp[(b * NSPLIT + 2) * per_b + e];
    const float4* p3 = (const float4*)&g_ctxp[(b * NSPLIT + 3) * per_b + e];
    float4 a = *p0, c = *p1, d = *p2, h = *p3;
    *(float4*)&g_ctx[b * per_b + e] =
        make_float4(a.x + c.x + d.x + h.x, a.y + c.y + d.y + h.y,
                    a.z + c.z + d.z + h.z, a.w + c.w + d.w + h.w);
}

// out[o][n] = sum_v wW[o][v] * ctx_t[n][v] + bW[o]     grid (50, 4, 2)
__global__ void __launch_bounds__(256) out_mma(
    const float* __restrict__ wW, const float* __restrict__ bW,
    float* __restrict__ out)
{
    const int b = blockIdx.z;
    mma_gemm_body(wW,
                  g_ctx + (size_t)b * HW_ * CV_,
                  out + (size_t)b * CO_ * HW_,
                  0, CV_, CV_, CV_, HW_, 1.0f, bW,
                  blockIdx.y * 128, blockIdx.x * 128);
}

// ---------------------------------------------------------------------------
// Kernel 1: k = relu(BN(Wk x + bk)) written transposed to g_kt,
//           v = Wv x + bv written to g_v.   grid (100, 4, 4)
// ---------------------------------------------------------------------------
__global__ void __launch_bounds__(256) kv_kernel(
    const float* __restrict__ x,
    const float* __restrict__ wk, const float* __restrict__ bk,
    const float* __restrict__ gamma, const float* __restrict__ beta,
    const float* __restrict__ rmean, const float* __restrict__ rvar,
    const float* __restrict__ wv, const float* __restrict__ bv)
{
    const int n0 = blockIdx.x * 64;
    const int m0 = blockIdx.y * 64;
    const int b  = blockIdx.z >> 1;
    const int isV = blockIdx.z & 1;
    const float* W  = isV ? wv : wk;
    const float* Xb = x + (size_t)b * C_ * HW_;

    __shared__ float As[16][68];
    __shared__ float Bs[16][68];

    const int tid = threadIdx.x;
    const int tx = tid & 15, ty = tid >> 4;

    float acc[4][4] = {};

    for (int k0 = 0; k0 < C_; k0 += 16) {
        {
            int m  = tid >> 2;
            int kg = (tid & 3) * 4;
            float4 f = *(const float4*)&W[(size_t)(m0 + m) * C_ + k0 + kg];
            As[kg + 0][m] = f.x; As[kg + 1][m] = f.y;
            As[kg + 2][m] = f.z; As[kg + 3][m] = f.w;
        }
        {
            int kk = tid >> 4;
            int ng = (tid & 15) * 4;
            *(float4*)&Bs[kk][ng] =
                *(const float4*)&Xb[(size_t)(k0 + kk) * HW_ + n0 + ng];
        }
        __syncthreads();
        #pragma unroll
        for (int kk = 0; kk < 16; kk++) {
            float4 a  = *(const float4*)&As[kk][ty * 4];
            float4 bb = *(const float4*)&Bs[kk][tx * 4];
            float av[4] = {a.x, a.y, a.z, a.w};
            float bv4[4] = {bb.x, bb.y, bb.z, bb.w};
            #pragma unroll
            for (int i = 0; i < 4; i++)
                #pragma unroll
                for (int j = 0; j < 4; j++)
                    acc[i][j] = fmaf(av[i], bv4[j], acc[i][j]);
        }
        __syncthreads();
    }

    if (isV) {
        float* out = g_v + (size_t)b * CV_ * HW_;
        #pragma unroll
        for (int i = 0; i < 4; i++) {
            int m = m0 + ty * 4 + i;
            float bias = bv[m];
            *(float4*)&out[(size_t)m * HW_ + n0 + tx * 4] =
                make_float4(acc[i][0] + bias, acc[i][1] + bias,
                            acc[i][2] + bias, acc[i][3] + bias);
        }
    } else {
        float* kt = g_kt + (size_t)b * HW_ * CK_;
        #pragma unroll
        for (int i = 0; i < 4; i++) {
            int m = m0 + ty * 4 + i;
            float bias = bk[m];
            float sc = gamma[m] / sqrtf(rvar[m] + BN_EPS);
            float mu = rmean[m];
            float be = beta[m];
            #pragma unroll
            for (int j = 0; j < 4; j++) {
                float t = acc[i][j] + bias;
                t = (t - mu) * sc + be;
                t = fmaxf(t, 0.f);
                kt[(size_t)(n0 + tx * 4 + j) * CK_ + m] = t;
            }
        }
    }
}

// ---------------------------------------------------------------------------
// Kernel 3: online row softmax (2 passes), in place.  grid (12800), 256 thr
// ---------------------------------------------------------------------------
__global__ void __launch_bounds__(256) softmax_kernel()
{
    const size_t row = blockIdx.x;
    float* S = g_sim + row * HW_;
    __shared__ float rm[256], rs[256];
    const int tid = threadIdx.x;

    float m = -1e30f, s = 0.f;
    for (int i = tid; i < HW_ / 4; i += 256) {
        float4 f = *(const float4*)&S[i * 4];
        float vmax = fmaxf(fmaxf(f.x, f.y), fmaxf(f.z, f.w));
        if (vmax > m) { s *= __expf(m - vmax); m = vmax; }
        s += __expf(f.x - m) + __expf(f.y - m) + __expf(f.z - m) + __expf(f.w - m);
    }
    rm[tid] = m; rs[tid] = s;
    __syncthreads();
    for (int st = 128; st > 0; st >>= 1) {
        if (tid < st) {
            float m1 = rm[tid], s1 = rs[tid];
            float m2 = rm[tid + st], s2 = rs[tid + st];
            float M = fmaxf(m1, m2);
            rm[tid] = M;
            rs[tid] = s1 * __expf(m1 - M) + s2 * __expf(m2 - M);
        }
        __syncthreads();
    }
    const float M = rm[0];
    const float inv = 1.f / rs[0];

    for (int i = tid; i < HW_ / 4; i += 256) {
        float4 f = *(const float4*)&S[i * 4];
        f.x = __expf(f.x - M) * inv;
        f.y = __expf(f.y - M) * inv;
        f.z = __expf(f.z - M) * inv;
        f.w = __expf(f.w - M) * inv;
        *(float4*)&S[i * 4] = f;
    }
}

// ---------------------------------------------------------------------------
// Launch
// ---------------------------------------------------------------------------
extern "C" void kernel_launch(void* const* d_in, const int* in_sizes, int n_in,
                              void* d_out, int out_size)
{
    const float* x     = (const float*)d_in[0];
    const float* wk    = (const float*)d_in[1];
    const float* bk    = (const float*)d_in[2];
    const float* gamma = (const float*)d_in[3];
    const float* beta  = (const float*)d_in[4];
    const float* rmean = (const float*)d_in[5];
    const float* rvar  = (const float*)d_in[6];
    const float* wv    = (const float*)d_in[7];
    const float* bv    = (const float*)d_in[8];
    const float* wW    = (const float*)d_in[9];
    const float* bW    = (const float*)d_in[10];
    float* out = (float*)d_out;

    dim3 blk(256);
    kv_kernel<<<dim3(100, 4, 4), blk>>>(x, wk, bk, gamma, beta, rmean, rvar, wv, bv);
    sim_mma<<<dim3(50, 50, 2), blk>>>();
    softmax_kernel<<<dim3(12800, 1, 1), blk>>>();
    ctx_mma<<<dim3(2, 50, 2 * NSPLIT), blk>>>();
    reduce_ctx<<<dim3(3200, 1, 1), blk>>>();
    out_mma<<<dim3(50, 4, 2), blk>>>(wW, bW, out);
}

// round 6
// speedup vs baseline: 2.9899x; 1.3149x over previous
#include <cuda_runtime.h>
#include <math.h>
#include <stdint.h>

#define BN_EPS 1e-5f

// Problem constants
#define B_   2
#define C_   512
#define HW_  6400
#define CK_  256
#define CV_  256
#define CO_  512
#define NSPLIT 4
#define KSPLIT (HW_ / NSPLIT)   // 1600
#define NT_  50                 // 6400 / 128 tiles per dim

// ---------------------------------------------------------------------------
// Scratch (device globals)
// ---------------------------------------------------------------------------
__device__ float g_kt  [(size_t)B_ * HW_ * CK_];           // K^T: [pixel][channel]
__device__ float g_v   [(size_t)B_ * CV_ * HW_];           // V:   [channel][pixel]
__device__ float g_sim [(size_t)B_ * HW_ * HW_];           // unnormalized exp(S - u_row)
__device__ float g_ctxp[(size_t)B_ * NSPLIT * HW_ * CV_];  // ctx partials
__device__ float g_ctx [(size_t)B_ * HW_ * CV_];           // ctx^T: [n][v] (normalized)
__device__ float g_rn  [(size_t)B_ * HW_];                 // ||k_r||^2
__device__ float g_gsq [B_];                               // max_r ||k_r||^2 per batch
__device__ float g_ps  [(size_t)B_ * HW_ * NT_];           // row-sum partials
__device__ float g_inv [(size_t)B_ * HW_];                 // 1/rowsum

// ---------------------------------------------------------------------------
// TF32 mma helpers
// ---------------------------------------------------------------------------
__device__ __forceinline__ uint32_t f2tf(float f) {
    uint32_t u;
    asm("cvt.rna.tf32.f32 %0, %1;" : "=r"(u) : "f"(f));
    return u;
}

__device__ __forceinline__ void mma_tf32(float* c, const uint32_t* a, const uint32_t* b) {
    asm volatile(
        "mma.sync.aligned.m16n8k8.row.col.f32.tf32.tf32.f32 "
        "{%0,%1,%2,%3}, {%4,%5,%6,%7}, {%8,%9}, {%0,%1,%2,%3};"
        : "+f"(c[0]), "+f"(c[1]), "+f"(c[2]), "+f"(c[3])
        : "r"(a[0]), "r"(a[1]), "r"(a[2]), "r"(a[3]), "r"(b[0]), "r"(b[1]));
}

// ---------------------------------------------------------------------------
// Shared TF32 GEMM body (128x128 tile, 8 warps), register-prefetch dbuf.
// C[m][n] = scale * sum_{k in [kb,ke)} A[m][k]*B[n][k]  (+bias[m])
// ---------------------------------------------------------------------------
__device__ __forceinline__ void mma_gemm_body(
    const float* __restrict__ A, const float* __restrict__ B,
    float* __restrict__ C, int kb, int ke,
    int lda, int ldb, int ldc, float scale, const float* __restrict__ bias,
    int m0, int n0)
{
    __shared__ uint32_t As[128][36];
    __shared__ uint32_t Bs[128][36];

    const int tid  = threadIdx.x;
    const int lane = tid & 31;
    const int wid  = tid >> 5;
    const int warpM0 = (wid & 3) * 32;
    const int warpN0 = (wid >> 2) * 64;
    const int t4 = lane >> 2;
    const int tm = lane & 3;

    const int lr = tid >> 1;
    const int lc = (tid & 1) * 16;

    const float* Abase = A + (size_t)(m0 + lr) * lda + lc;
    const float* Bbase = B + (size_t)(n0 + lr) * ldb + lc;

    float acc[2][8][4] = {};
    float4 ra[4], rb[4];

    #pragma unroll
    for (int i = 0; i < 4; i++) {
        ra[i] = *(const float4*)(Abase + kb + i * 4);
        rb[i] = *(const float4*)(Bbase + kb + i * 4);
    }

    for (int k0 = kb; k0 < ke; k0 += 32) {
        #pragma unroll
        for (int i = 0; i < 4; i++) {
            *(uint4*)&As[lr][lc + i * 4] =
                make_uint4(f2tf(ra[i].x), f2tf(ra[i].y), f2tf(ra[i].z), f2tf(ra[i].w));
            *(uint4*)&Bs[lr][lc + i * 4] =
                make_uint4(f2tf(rb[i].x), f2tf(rb[i].y), f2tf(rb[i].z), f2tf(rb[i].w));
        }
        __syncthreads();

        if (k0 + 32 < ke) {
            #pragma unroll
            for (int i = 0; i < 4; i++) {
                ra[i] = *(const float4*)(Abase + k0 + 32 + i * 4);
                rb[i] = *(const float4*)(Bbase + k0 + 32 + i * 4);
            }
        }

        #pragma unroll
        for (int s = 0; s < 4; s++) {
            uint32_t a[2][4], b[8][2];
            #pragma unroll
            for (int i = 0; i < 2; i++) {
                int r = warpM0 + i * 16 + t4;
                a[i][0] = As[r][s * 8 + tm];
                a[i][1] = As[r + 8][s * 8 + tm];
                a[i][2] = As[r][s * 8 + tm + 4];
                a[i][3] = As[r + 8][s * 8 + tm + 4];
            }
            #pragma unroll
            for (int j = 0; j < 8; j++) {
                int r = warpN0 + j * 8 + t4;
                b[j][0] = Bs[r][s * 8 + tm];
                b[j][1] = Bs[r][s * 8 + tm + 4];
            }
            #pragma unroll
            for (int i = 0; i < 2; i++)
                #pragma unroll
                for (int j = 0; j < 8; j++)
                    mma_tf32(acc[i][j], a[i], b[j]);
        }
        __syncthreads();
    }

    #pragma unroll
    for (int i = 0; i < 2; i++) {
        int r1 = m0 + warpM0 + i * 16 + t4;
        int r2 = r1 + 8;
        float b1 = bias ? bias[r1] : 0.f;
        float b2 = bias ? bias[r2] : 0.f;
        #pragma unroll
        for (int j = 0; j < 8; j++) {
            int cg = n0 + warpN0 + j * 8 + tm * 2;
            *(float2*)&C[(size_t)r1 * ldc + cg] =
                make_float2(acc[i][j][0] * scale + b1, acc[i][j][1] * scale + b1);
            *(float2*)&C[(size_t)r2 * ldc + cg] =
                make_float2(acc[i][j][2] * scale + b2, acc[i][j][3] * scale + b2);
        }
    }
}

// ---------------------------------------------------------------------------
// Symmetric sim with fused exp + partial row sums.
// Upper-triangle tiles only; mirror written in epilogue.
// grid (1275, 1, 2), 256 threads.
// ---------------------------------------------------------------------------
__global__ void __launch_bounds__(256) sim_sym()
{
    // decode upper-triangle tile pair (ti <= tj)
    int rem = blockIdx.x, ti = 0;
    while (rem >= NT_ - ti) { rem -= NT_ - ti; ti++; }
    const int tj = ti + rem;
    const int b  = blockIdx.z;
    const int m0 = ti * 128, n0 = tj * 128;

    const float* Kt = g_kt + (size_t)b * HW_ * CK_;

    __shared__ uint32_t As[128][36];
    __shared__ uint32_t Bs[128][36];
    __shared__ float ps1[128][2];
    __shared__ float ps2[128][4];

    const int tid  = threadIdx.x;
    const int lane = tid & 31;
    const int wid  = tid >> 5;
    const int warpM0 = (wid & 3) * 32;
    const int warpN0 = (wid >> 2) * 64;
    const int t4 = lane >> 2;
    const int tm = lane & 3;

    const int lr = tid >> 1;
    const int lc = (tid & 1) * 16;

    const float* Abase = Kt + (size_t)(m0 + lr) * CK_ + lc;
    const float* Bbase = Kt + (size_t)(n0 + lr) * CK_ + lc;

    float acc[2][8][4] = {};
    float4 ra[4], rb[4];

    #pragma unroll
    for (int i = 0; i < 4; i++) {
        ra[i] = *(const float4*)(Abase + i * 4);
        rb[i] = *(const float4*)(Bbase + i * 4);
    }

    for (int k0 = 0; k0 < CK_; k0 += 32) {
        #pragma unroll
        for (int i = 0; i < 4; i++) {
            *(uint4*)&As[lr][lc + i * 4] =
                make_uint4(f2tf(ra[i].x), f2tf(ra[i].y), f2tf(ra[i].z), f2tf(ra[i].w));
            *(uint4*)&Bs[lr][lc + i * 4] =
                make_uint4(f2tf(rb[i].x), f2tf(rb[i].y), f2tf(rb[i].z), f2tf(rb[i].w));
        }
        __syncthreads();

        if (k0 + 32 < CK_) {
            #pragma unroll
            for (int i = 0; i < 4; i++) {
                ra[i] = *(const float4*)(Abase + k0 + 32 + i * 4);
                rb[i] = *(const float4*)(Bbase + k0 + 32 + i * 4);
            }
        }

        #pragma unroll
        for (int s = 0; s < 4; s++) {
            uint32_t a[2][4], b[8][2];
            #pragma unroll
            for (int i = 0; i < 2; i++) {
                int r = warpM0 + i * 16 + t4;
                a[i][0] = As[r][s * 8 + tm];
                a[i][1] = As[r + 8][s * 8 + tm];
                a[i][2] = As[r][s * 8 + tm + 4];
                a[i][3] = As[r + 8][s * 8 + tm + 4];
            }
            #pragma unroll
            for (int j = 0; j < 8; j++) {
                int r = warpN0 + j * 8 + t4;
                b[j][0] = Bs[r][s * 8 + tm];
                b[j][1] = Bs[r][s * 8 + tm + 4];
            }
            #pragma unroll
            for (int i = 0; i < 2; i++)
                #pragma unroll
                for (int j = 0; j < 8; j++)
                    mma_tf32(acc[i][j], a[i], b[j]);
        }
        __syncthreads();
    }

    // ------------- epilogue: exp + partial sums + mirror -------------
    float* S = g_sim + (size_t)b * HW_ * HW_;
    const float* rn = g_rn + (size_t)b * HW_;
    const float Gsq = g_gsq[b];
    const float SC = 0.0625f;

    // primary tile: e = exp(s*SC - u[row]); row-sum partials
    float rs[2][2] = {};
    #pragma unroll
    for (int i = 0; i < 2; i++) {
        const int rl1 = warpM0 + i * 16 + t4;
        const int rl2 = rl1 + 8;
        const float u1 = sqrtf(rn[m0 + rl1] * Gsq) * SC;
        const float u2 = sqrtf(rn[m0 + rl2] * Gsq) * SC;
        #pragma unroll
        for (int j = 0; j < 8; j++) {
            const int cg = n0 + warpN0 + j * 8 + tm * 2;
            float e0 = __expf(acc[i][j][0] * SC - u1);
            float e1 = __expf(acc[i][j][1] * SC - u1);
            float e2 = __expf(acc[i][j][2] * SC - u2);
            float e3 = __expf(acc[i][j][3] * SC - u2);
            rs[i][0] += e0 + e1;
            rs[i][1] += e2 + e3;
            *(float2*)&S[(size_t)(m0 + rl1) * HW_ + cg] = make_float2(e0, e1);
            *(float2*)&S[(size_t)(m0 + rl2) * HW_ + cg] = make_float2(e2, e3);
        }
    }
    #pragma unroll
    for (int i = 0; i < 2; i++)
        #pragma unroll
        for (int r = 0; r < 2; r++) {
            rs[i][r] += __shfl_xor_sync(0xFFFFFFFFu, rs[i][r], 1);
            rs[i][r] += __shfl_xor_sync(0xFFFFFFFFu, rs[i][r], 2);
        }
    if (tm == 0) {
        #pragma unroll
        for (int i = 0; i < 2; i++) {
            ps1[warpM0 + i * 16 + t4][warpN0 >> 6]     = rs[i][0];
            ps1[warpM0 + i * 16 + t4 + 8][warpN0 >> 6] = rs[i][1];
        }
    }
    __syncthreads();
    if (tid < 128) {
        g_ps[((size_t)b * HW_ + m0 + tid) * NT_ + tj] = ps1[tid][0] + ps1[tid][1];
    }

    // mirror tile (off-diagonal only): S[n][m] = exp(s*SC - u[n]); col-sum partials
    if (ti != tj) {
        float cs[8][2] = {};
        #pragma unroll
        for (int j = 0; j < 8; j++) {
            const int cl = warpN0 + j * 8 + tm * 2;     // local col
            const float uc0 = sqrtf(rn[n0 + cl] * Gsq) * SC;
            const float uc1 = sqrtf(rn[n0 + cl + 1] * Gsq) * SC;
            #pragma unroll
            for (int i = 0; i < 2; i++) {
                const int r1g = m0 + warpM0 + i * 16 + t4;
                const int r2g = r1g + 8;
                float f0 = __expf(acc[i][j][0] * SC - uc0);
                float f1 = __expf(acc[i][j][1] * SC - uc1);
                float f2 = __expf(acc[i][j][2] * SC - uc0);
                float f3 = __expf(acc[i][j][3] * SC - uc1);
                S[(size_t)(n0 + cl) * HW_ + r1g]     = f0;
                S[(size_t)(n0 + cl + 1) * HW_ + r1g] = f1;
                S[(size_t)(n0 + cl) * HW_ + r2g]     = f2;
                S[(size_t)(n0 + cl + 1) * HW_ + r2g] = f3;
                cs[j][0] += f0 + f2;
                cs[j][1] += f1 + f3;
            }
        }
        #pragma unroll
        for (int j = 0; j < 8; j++)
            #pragma unroll
            for (int c = 0; c < 2; c++) {
                cs[j][c] += __shfl_xor_sync(0xFFFFFFFFu, cs[j][c], 4);
                cs[j][c] += __shfl_xor_sync(0xFFFFFFFFu, cs[j][c], 8);
                cs[j][c] += __shfl_xor_sync(0xFFFFFFFFu, cs[j][c], 16);
            }
        if (t4 == 0) {
            #pragma unroll
            for (int j = 0; j < 8; j++) {
                ps2[warpN0 + j * 8 + tm * 2][wid & 3]     = cs[j][0];
                ps2[warpN0 + j * 8 + tm * 2 + 1][wid & 3] = cs[j][1];
            }
        }
        __syncthreads();
        if (tid < 128) {
            g_ps[((size_t)b * HW_ + n0 + tid) * NT_ + ti] =
                ps2[tid][0] + ps2[tid][1] + ps2[tid][2] + ps2[tid][3];
        }
    }
}

// ---------------------------------------------------------------------------
// Row squared norms of Kt: one warp per row.  grid (1600), 256 thr (8 warps)
// ---------------------------------------------------------------------------
__global__ void __launch_bounds__(256) norm_kernel()
{
    const int w = threadIdx.x >> 5;
    const int lane = threadIdx.x & 31;
    const int row = blockIdx.x * 8 + w;
    const float* p = g_kt + (size_t)row * CK_ + lane * 8;
    float4 a = *(const float4*)p;
    float4 b = *(const float4*)(p + 4);
    float s = a.x*a.x + a.y*a.y + a.z*a.z + a.w*a.w
            + b.x*b.x + b.y*b.y + b.z*b.z + b.w*b.w;
    #pragma unroll
    for (int d = 16; d > 0; d >>= 1) s += __shfl_xor_sync(0xFFFFFFFFu, s, d);
    if (lane == 0) g_rn[row] = s;
}

// Per-batch max of g_rn.  grid (2), 256 threads
__global__ void __launch_bounds__(256) gmax_kernel()
{
    const int b = blockIdx.x;
    const int tid = threadIdx.x;
    __shared__ float red[256];
    float m = 0.f;
    for (int i = tid; i < HW_; i += 256) m = fmaxf(m, g_rn[(size_t)b * HW_ + i]);
    red[tid] = m;
    __syncthreads();
    for (int s = 128; s > 0; s >>= 1) {
        if (tid < s) red[tid] = fmaxf(red[tid], red[tid + s]);
        __syncthreads();
    }
    if (tid == 0) g_gsq[b] = red[0];
}

// g_inv[r] = 1 / sum_j g_ps[r][j].  grid (50), 256 threads
__global__ void __launch_bounds__(256) rowinv_kernel()
{
    const int r = blockIdx.x * 256 + threadIdx.x;   // 0..12799
    const float* p = g_ps + (size_t)r * NT_;
    float s = 0.f;
    #pragma unroll
    for (int j = 0; j < NT_; j++) s += p[j];
    g_inv[r] = 1.f / s;
}

// ctx_t[n][v] partial = sum_{m in split} P[n][m] * V[v][m]     grid (2, 50, 8)
__global__ void __launch_bounds__(256) ctx_mma()
{
    const int b = blockIdx.z >> 2;
    const int sp = blockIdx.z & 3;
    mma_gemm_body(g_sim + (size_t)b * HW_ * HW_,
                  g_v + (size_t)b * CV_ * HW_,
                  g_ctxp + (size_t)(b * NSPLIT + sp) * HW_ * CV_,
                  sp * KSPLIT, (sp + 1) * KSPLIT,
                  HW_, HW_, CV_, 1.0f, nullptr,
                  blockIdx.y * 128, blockIdx.x * 128);
}

// g_ctx = (sum of 4 partials) * inv[n]      grid (3200), 256 threads
__global__ void __launch_bounds__(256) reduce_ctx()
{
    const size_t f = (size_t)blockIdx.x * 256 + threadIdx.x;
    const size_t per_b = (size_t)HW_ * CV_;
    const size_t g = f * 4;
    const size_t b = g / per_b;
    const size_t e = g % per_b;
    const size_t n = e / CV_;
    const float inv = g_inv[b * HW_ + n];
    const float4 a = *(const float4*)&g_ctxp[(b * NSPLIT + 0) * per_b + e];
    const float4 c = *(const float4*)&g_ctxp[(b * NSPLIT + 1) * per_b + e];
    const float4 d = *(const float4*)&g_ctxp[(b * NSPLIT + 2) * per_b + e];
    const float4 h = *(const float4*)&g_ctxp[(b * NSPLIT + 3) * per_b + e];
    *(float4*)&g_ctx[b * per_b + e] =
        make_float4((a.x + c.x + d.x + h.x) * inv, (a.y + c.y + d.y + h.y) * inv,
                    (a.z + c.z + d.z + h.z) * inv, (a.w + c.w + d.w + h.w) * inv);
}

// out[o][n] = sum_v wW[o][v] * ctx_t[n][v] + bW[o]     grid (50, 4, 2)
__global__ void __launch_bounds__(256) out_mma(
    const float* __restrict__ wW, const float* __restrict__ bW,
    float* __restrict__ out)
{
    const int b = blockIdx.z;
    mma_gemm_body(wW,
                  g_ctx + (size_t)b * HW_ * CV_,
                  out + (size_t)b * CO_ * HW_,
                  0, CV_, CV_, CV_, HW_, 1.0f, bW,
                  blockIdx.y * 128, blockIdx.x * 128);
}

// ---------------------------------------------------------------------------
// Kernel 1: k = relu(BN(Wk x + bk)) written transposed to g_kt,
//           v = Wv x + bv written to g_v.   grid (100, 4, 4)
// ---------------------------------------------------------------------------
__global__ void __launch_bounds__(256) kv_kernel(
    const float* __restrict__ x,
    const float* __restrict__ wk, const float* __restrict__ bk,
    const float* __restrict__ gamma, const float* __restrict__ beta,
    const float* __restrict__ rmean, const float* __restrict__ rvar,
    const float* __restrict__ wv, const float* __restrict__ bv)
{
    const int n0 = blockIdx.x * 64;
    const int m0 = blockIdx.y * 64;
    const int b  = blockIdx.z >> 1;
    const int isV = blockIdx.z & 1;
    const float* W  = isV ? wv : wk;
    const float* Xb = x + (size_t)b * C_ * HW_;

    __shared__ float As[16][68];
    __shared__ float Bs[16][68];

    const int tid = threadIdx.x;
    const int tx = tid & 15, ty = tid >> 4;

    float acc[4][4] = {};

    for (int k0 = 0; k0 < C_; k0 += 16) {
        {
            int m  = tid >> 2;
            int kg = (tid & 3) * 4;
            float4 f = *(const float4*)&W[(size_t)(m0 + m) * C_ + k0 + kg];
            As[kg + 0][m] = f.x; As[kg + 1][m] = f.y;
            As[kg + 2][m] = f.z; As[kg + 3][m] = f.w;
        }
        {
            int kk = tid >> 4;
            int ng = (tid & 15) * 4;
            *(float4*)&Bs[kk][ng] =
                *(const float4*)&Xb[(size_t)(k0 + kk) * HW_ + n0 + ng];
        }
        __syncthreads();
        #pragma unroll
        for (int kk = 0; kk < 16; kk++) {
            float4 a  = *(const float4*)&As[kk][ty * 4];
            float4 bb = *(const float4*)&Bs[kk][tx * 4];
            float av[4] = {a.x, a.y, a.z, a.w};
            float bv4[4] = {bb.x, bb.y, bb.z, bb.w};
            #pragma unroll
            for (int i = 0; i < 4; i++)
                #pragma unroll
                for (int j = 0; j < 4; j++)
                    acc[i][j] = fmaf(av[i], bv4[j], acc[i][j]);
        }
        __syncthreads();
    }

    if (isV) {
        float* out = g_v + (size_t)b * CV_ * HW_;
        #pragma unroll
        for (int i = 0; i < 4; i++) {
            int m = m0 + ty * 4 + i;
            float bias = bv[m];
            *(float4*)&out[(size_t)m * HW_ + n0 + tx * 4] =
                make_float4(acc[i][0] + bias, acc[i][1] + bias,
                            acc[i][2] + bias, acc[i][3] + bias);
        }
    } else {
        float* kt = g_kt + (size_t)b * HW_ * CK_;
        #pragma unroll
        for (int i = 0; i < 4; i++) {
            int m = m0 + ty * 4 + i;
            float bias = bk[m];
            float sc = gamma[m] / sqrtf(rvar[m] + BN_EPS);
            float mu = rmean[m];
            float be = beta[m];
            #pragma unroll
            for (int j = 0; j < 4; j++) {
                float t = acc[i][j] + bias;
                t = (t - mu) * sc + be;
                t = fmaxf(t, 0.f);
                kt[(size_t)(n0 + tx * 4 + j) * CK_ + m] = t;
            }
        }
    }
}

// ---------------------------------------------------------------------------
// Launch
// ---------------------------------------------------------------------------
extern "C" void kernel_launch(void* const* d_in, const int* in_sizes, int n_in,
                              void* d_out, int out_size)
{
    const float* x     = (const float*)d_in[0];
    const float* wk    = (const float*)d_in[1];
    const float* bk    = (const float*)d_in[2];
    const float* gamma = (const float*)d_in[3];
    const float* beta  = (const float*)d_in[4];
    const float* rmean = (const float*)d_in[5];
    const float* rvar  = (const float*)d_in[6];
    const float* wv    = (const float*)d_in[7];
    const float* bv    = (const float*)d_in[8];
    const float* wW    = (const float*)d_in[9];
    const float* bW    = (const float*)d_in[10];
    float* out = (float*)d_out;

    dim3 blk(256);
    kv_kernel<<<dim3(100, 4, 4), blk>>>(x, wk, bk, gamma, beta, rmean, rvar, wv, bv);
    norm_kernel<<<dim3(1600, 1, 1), blk>>>();
    gmax_kernel<<<dim3(2, 1, 1), blk>>>();
    sim_sym<<<dim3(1275, 1, 2), blk>>>();
    rowinv_kernel<<<dim3(50, 1, 1), blk>>>();
    ctx_mma<<<dim3(2, 50, 2 * NSPLIT), blk>>>();
    reduce_ctx<<<dim3(3200, 1, 1), blk>>>();
    out_mma<<<dim3(50, 4, 2), blk>>>(wW, bW, out);
}

// round 7
// speedup vs baseline: 3.4373x; 1.1496x over previous
#include <cuda_runtime.h>
#include <math.h>
#include <stdint.h>

#define BN_EPS 1e-5f

// Problem constants
#define B_   2
#define C_   512
#define HW_  6400
#define CK_  256
#define CV_  256
#define CO_  512
#define NSPLIT 4
#define KSPLIT (HW_ / NSPLIT)   // 1600
#define NT_  50                 // 6400 / 128 tiles per dim

#define NSTAGE 3
#define STAGE_F (2 * 128 * 36)          // floats per stage (A+B)
#define SMEM_DYN (NSTAGE * STAGE_F * 4) // 110592 bytes

// ---------------------------------------------------------------------------
// Scratch (device globals)
// ---------------------------------------------------------------------------
__device__ float g_xt  [(size_t)B_ * HW_ * C_];            // x^T rounded: [b][n][c]
__device__ float g_wr  [3 * 131072];                       // rounded wk | wv | wW
__device__ float g_kt  [(size_t)B_ * HW_ * CK_];           // K^T rounded: [pixel][channel]
__device__ float g_v   [(size_t)B_ * CV_ * HW_];           // V rounded: [channel][pixel]
__device__ float g_sim [(size_t)B_ * HW_ * HW_];           // exp(S - u_row), rounded
__device__ float g_ctxp[(size_t)B_ * NSPLIT * HW_ * CV_];  // ctx partials (fp32)
__device__ float g_ctx [(size_t)B_ * HW_ * CV_];           // ctx^T rounded: [n][v]
__device__ float g_rn  [(size_t)B_ * HW_];                 // ||k_r||^2
__device__ float g_gsq [B_];                               // max_r ||k_r||^2
__device__ float g_ps  [(size_t)B_ * HW_ * NT_];           // row-sum partials
__device__ float g_inv [(size_t)B_ * HW_];                 // 1/rowsum

// ---------------------------------------------------------------------------
// Helpers
// ---------------------------------------------------------------------------
__device__ __forceinline__ uint32_t f2tf(float f) {
    uint32_t u;
    asm("cvt.rna.tf32.f32 %0, %1;" : "=r"(u) : "f"(f));
    return u;
}
__device__ __forceinline__ float roundtf(float f) { return __uint_as_float(f2tf(f)); }

__device__ __forceinline__ void mma_tf32(float* c, const uint32_t* a, const uint32_t* b) {
    asm volatile(
        "mma.sync.aligned.m16n8k8.row.col.f32.tf32.tf32.f32 "
        "{%0,%1,%2,%3}, {%4,%5,%6,%7}, {%8,%9}, {%0,%1,%2,%3};"
        : "+f"(c[0]), "+f"(c[1]), "+f"(c[2]), "+f"(c[3])
        : "r"(a[0]), "r"(a[1]), "r"(a[2]), "r"(a[3]), "r"(b[0]), "r"(b[1]));
}

__device__ __forceinline__ void cp16(uint32_t saddr, const float* g) {
    asm volatile("cp.async.cg.shared.global [%0], [%1], 16;" :: "r"(saddr), "l"(g));
}
__device__ __forceinline__ void cp_commit() {
    asm volatile("cp.async.commit_group;");
}
template<int N> __device__ __forceinline__ void cp_wait() {
    asm volatile("cp.async.wait_group %0;" :: "n"(N));
}

// ---------------------------------------------------------------------------
// Pipelined TF32 mainloop: acc[m][n] += sum_{k in [kb,ke)} A[m][k]*B[n][k]
// A, B pre-offset to the tile's first row; operands pre-rounded to tf32.
// 128x128 tile, 8 warps; dynamic smem [NSTAGE][A 128x36 | B 128x36].
// ---------------------------------------------------------------------------
__device__ __forceinline__ void mma_mainloop(
    const float* __restrict__ A, const float* __restrict__ B,
    int lda, int ldb, int kb, int ke, float acc[2][8][4])
{
    extern __shared__ float sm[];
    const int tid  = threadIdx.x;
    const int lane = tid & 31;
    const int wid  = tid >> 5;
    const int warpM0 = (wid & 3) * 32;
    const int warpN0 = (wid >> 2) * 64;
    const int t4 = lane >> 2;
    const int tm = lane & 3;

    const int lr = tid >> 1;
    const int lc = (tid & 1) * 16;

    const float* Ar = A + (size_t)lr * lda + lc;
    const float* Br = B + (size_t)lr * ldb + lc;

    const int ktiles = (ke - kb) / 32;

#define ISSUE_TILE(stage, k0) do {                                          \
        float* As_ = sm + (stage) * STAGE_F;                                \
        float* Bs_ = As_ + 128 * 36;                                        \
        uint32_t sa_ = (uint32_t)__cvta_generic_to_shared(&As_[lr*36+lc]);  \
        uint32_t sb_ = (uint32_t)__cvta_generic_to_shared(&Bs_[lr*36+lc]);  \
        const float* Ap_ = Ar + (k0);                                       \
        const float* Bp_ = Br + (k0);                                       \
        cp16(sa_ +  0, Ap_ +  0); cp16(sb_ +  0, Bp_ +  0);                 \
        cp16(sa_ + 16, Ap_ +  4); cp16(sb_ + 16, Bp_ +  4);                 \
        cp16(sa_ + 32, Ap_ +  8); cp16(sb_ + 32, Bp_ +  8);                 \
        cp16(sa_ + 48, Ap_ + 12); cp16(sb_ + 48, Bp_ + 12);                 \
    } while (0)

    // prologue: preload NSTAGE-1 tiles
    ISSUE_TILE(0, kb);
    cp_commit();
    if (ktiles > 1) ISSUE_TILE(1, kb + 32);
    cp_commit();

    for (int t = 0; t < ktiles; t++) {
        const int cur = t % NSTAGE;
        if (t + 2 < ktiles) ISSUE_TILE((t + 2) % NSTAGE, kb + (t + 2) * 32);
        cp_commit();
        cp_wait<2>();
        __syncthreads();

        const float* As = sm + cur * STAGE_F;
        const float* Bs = As + 128 * 36;

        #pragma unroll
        for (int s = 0; s < 4; s++) {
            uint32_t a[2][4], b[8][2];
            #pragma unroll
            for (int i = 0; i < 2; i++) {
                int r = warpM0 + i * 16 + t4;
                a[i][0] = __float_as_uint(As[r * 36 + s * 8 + tm]);
                a[i][1] = __float_as_uint(As[(r + 8) * 36 + s * 8 + tm]);
                a[i][2] = __float_as_uint(As[r * 36 + s * 8 + tm + 4]);
                a[i][3] = __float_as_uint(As[(r + 8) * 36 + s * 8 + tm + 4]);
            }
            #pragma unroll
            for (int j = 0; j < 8; j++) {
                int r = warpN0 + j * 8 + t4;
                b[j][0] = __float_as_uint(Bs[r * 36 + s * 8 + tm]);
                b[j][1] = __float_as_uint(Bs[r * 36 + s * 8 + tm + 4]);
            }
            #pragma unroll
            for (int i = 0; i < 2; i++)
                #pragma unroll
                for (int j = 0; j < 8; j++)
                    mma_tf32(acc[i][j], a[i], b[j]);
        }
        __syncthreads();
    }
#undef ISSUE_TILE
}

// ---------------------------------------------------------------------------
// Round + transpose x: [b][c][n] -> g_xt [b][n][c].  grid (200,16,2), 32x8 thr
// ---------------------------------------------------------------------------
__global__ void __launch_bounds__(256) transpose_x(const float* __restrict__ x)
{
    __shared__ float t[32][33];
    const int n0 = blockIdx.x * 32;
    const int c0 = blockIdx.y * 32;
    const int b  = blockIdx.z;
    const int tx = threadIdx.x, ty = threadIdx.y;

    #pragma unroll
    for (int j = 0; j < 4; j++) {
        int c = c0 + ty + j * 8;
        t[ty + j * 8][tx] = x[((size_t)b * C_ + c) * HW_ + n0 + tx];
    }
    __syncthreads();
    #pragma unroll
    for (int j = 0; j < 4; j++) {
        int n = n0 + ty + j * 8;
        g_xt[((size_t)b * HW_ + n) * C_ + c0 + tx] = roundtf(t[tx][ty + j * 8]);
    }
}

// Round weight matrices into g_wr.  grid (1536), 256 thr
__global__ void __launch_bounds__(256) round_w(
    const float* __restrict__ wk, const float* __restrict__ wv,
    const float* __restrict__ wW)
{
    const int i = blockIdx.x * 256 + threadIdx.x;   // 0..393215
    const float* src = (i < 131072) ? (wk + i)
                     : (i < 262144) ? (wv + i - 131072)
                                    : (wW + i - 262144);
    g_wr[i] = roundtf(*src);
}

// ---------------------------------------------------------------------------
// kv via mma: out ch x pixels.  grid (50, 2, 4)  z = b*2 + isV
// ---------------------------------------------------------------------------
__global__ void __launch_bounds__(256) kv_mma(
    const float* __restrict__ bk,
    const float* __restrict__ gamma, const float* __restrict__ beta,
    const float* __restrict__ rmean, const float* __restrict__ rvar,
    const float* __restrict__ bv)
{
    const int n0 = blockIdx.x * 128;
    const int m0 = blockIdx.y * 128;
    const int b  = blockIdx.z >> 1;
    const int isV = blockIdx.z & 1;

    const float* A = g_wr + (size_t)isV * 131072 + (size_t)m0 * C_;
    const float* B = g_xt + ((size_t)b * HW_ + n0) * C_;

    float acc[2][8][4] = {};
    mma_mainloop(A, B, C_, C_, 0, C_, acc);

    const int lane = threadIdx.x & 31;
    const int wid  = threadIdx.x >> 5;
    const int warpM0 = (wid & 3) * 32;
    const int warpN0 = (wid >> 2) * 64;
    const int t4 = lane >> 2;
    const int tm = lane & 3;

    if (isV) {
        float* V = g_v + (size_t)b * CV_ * HW_;
        #pragma unroll
        for (int i = 0; i < 2; i++) {
            int r1 = m0 + warpM0 + i * 16 + t4;
            int r2 = r1 + 8;
            float b1 = bv[r1], b2 = bv[r2];
            #pragma unroll
            for (int j = 0; j < 8; j++) {
                int cg = n0 + warpN0 + j * 8 + tm * 2;
                *(float2*)&V[(size_t)r1 * HW_ + cg] =
                    make_float2(roundtf(acc[i][j][0] + b1), roundtf(acc[i][j][1] + b1));
                *(float2*)&V[(size_t)r2 * HW_ + cg] =
                    make_float2(roundtf(acc[i][j][2] + b2), roundtf(acc[i][j][3] + b2));
            }
        }
    } else {
        float* kt = g_kt + (size_t)b * HW_ * CK_;
        #pragma unroll
        for (int i = 0; i < 2; i++) {
            int r1 = m0 + warpM0 + i * 16 + t4;
            int r2 = r1 + 8;
            float bb1 = bk[r1], bb2 = bk[r2];
            float sc1 = gamma[r1] / sqrtf(rvar[r1] + BN_EPS);
            float sc2 = gamma[r2] / sqrtf(rvar[r2] + BN_EPS);
            float mu1 = rmean[r1], mu2 = rmean[r2];
            float be1 = beta[r1],  be2 = beta[r2];
            #pragma unroll
            for (int j = 0; j < 8; j++) {
                int cg = n0 + warpN0 + j * 8 + tm * 2;
                float t0 = fmaxf((acc[i][j][0] + bb1 - mu1) * sc1 + be1, 0.f);
                float t1 = fmaxf((acc[i][j][1] + bb1 - mu1) * sc1 + be1, 0.f);
                float t2 = fmaxf((acc[i][j][2] + bb2 - mu2) * sc2 + be2, 0.f);
                float t3 = fmaxf((acc[i][j][3] + bb2 - mu2) * sc2 + be2, 0.f);
                kt[(size_t)cg * CK_ + r1]       = roundtf(t0);
                kt[(size_t)(cg + 1) * CK_ + r1] = roundtf(t1);
                kt[(size_t)cg * CK_ + r2]       = roundtf(t2);
                kt[(size_t)(cg + 1) * CK_ + r2] = roundtf(t3);
            }
        }
    }
}

// ---------------------------------------------------------------------------
// Symmetric sim with fused exp + partial sums.  grid (1275, 1, 2)
// ---------------------------------------------------------------------------
__global__ void __launch_bounds__(256) sim_sym()
{
    int rem = blockIdx.x, ti = 0;
    while (rem >= NT_ - ti) { rem -= NT_ - ti; ti++; }
    const int tj = ti + rem;
    const int b  = blockIdx.z;
    const int m0 = ti * 128, n0 = tj * 128;

    const float* Kt = g_kt + (size_t)b * HW_ * CK_;

    __shared__ float ps1[128][2];
    __shared__ float ps2[128][4];

    float acc[2][8][4] = {};
    mma_mainloop(Kt + (size_t)m0 * CK_, Kt + (size_t)n0 * CK_,
                 CK_, CK_, 0, CK_, acc);

    const int tid  = threadIdx.x;
    const int lane = tid & 31;
    const int wid  = tid >> 5;
    const int warpM0 = (wid & 3) * 32;
    const int warpN0 = (wid >> 2) * 64;
    const int t4 = lane >> 2;
    const int tm = lane & 3;

    float* S = g_sim + (size_t)b * HW_ * HW_;
    const float* rn = g_rn + (size_t)b * HW_;
    const float Gsq = g_gsq[b];
    const float SC = 0.0625f;

    // primary tile
    float rs[2][2] = {};
    #pragma unroll
    for (int i = 0; i < 2; i++) {
        const int rl1 = warpM0 + i * 16 + t4;
        const int rl2 = rl1 + 8;
        const float u1 = sqrtf(rn[m0 + rl1] * Gsq) * SC;
        const float u2 = sqrtf(rn[m0 + rl2] * Gsq) * SC;
        #pragma unroll
        for (int j = 0; j < 8; j++) {
            const int cg = n0 + warpN0 + j * 8 + tm * 2;
            float e0 = __expf(acc[i][j][0] * SC - u1);
            float e1 = __expf(acc[i][j][1] * SC - u1);
            float e2 = __expf(acc[i][j][2] * SC - u2);
            float e3 = __expf(acc[i][j][3] * SC - u2);
            rs[i][0] += e0 + e1;
            rs[i][1] += e2 + e3;
            *(float2*)&S[(size_t)(m0 + rl1) * HW_ + cg] =
                make_float2(roundtf(e0), roundtf(e1));
            *(float2*)&S[(size_t)(m0 + rl2) * HW_ + cg] =
                make_float2(roundtf(e2), roundtf(e3));
        }
    }
    #pragma unroll
    for (int i = 0; i < 2; i++)
        #pragma unroll
        for (int r = 0; r < 2; r++) {
            rs[i][r] += __shfl_xor_sync(0xFFFFFFFFu, rs[i][r], 1);
            rs[i][r] += __shfl_xor_sync(0xFFFFFFFFu, rs[i][r], 2);
        }
    if (tm == 0) {
        #pragma unroll
        for (int i = 0; i < 2; i++) {
            ps1[warpM0 + i * 16 + t4][warpN0 >> 6]     = rs[i][0];
            ps1[warpM0 + i * 16 + t4 + 8][warpN0 >> 6] = rs[i][1];
        }
    }
    __syncthreads();
    if (tid < 128) {
        g_ps[((size_t)b * HW_ + m0 + tid) * NT_ + tj] = ps1[tid][0] + ps1[tid][1];
    }

    // mirror tile
    if (ti != tj) {
        float cs[8][2] = {};
        #pragma unroll
        for (int j = 0; j < 8; j++) {
            const int cl = warpN0 + j * 8 + tm * 2;
            const float uc0 = sqrtf(rn[n0 + cl] * Gsq) * SC;
            const float uc1 = sqrtf(rn[n0 + cl + 1] * Gsq) * SC;
            #pragma unroll
            for (int i = 0; i < 2; i++) {
                const int r1g = m0 + warpM0 + i * 16 + t4;
                const int r2g = r1g + 8;
                float f0 = __expf(acc[i][j][0] * SC - uc0);
                float f1 = __expf(acc[i][j][1] * SC - uc1);
                float f2 = __expf(acc[i][j][2] * SC - uc0);
                float f3 = __expf(acc[i][j][3] * SC - uc1);
                S[(size_t)(n0 + cl) * HW_ + r1g]     = roundtf(f0);
                S[(size_t)(n0 + cl + 1) * HW_ + r1g] = roundtf(f1);
                S[(size_t)(n0 + cl) * HW_ + r2g]     = roundtf(f2);
                S[(size_t)(n0 + cl + 1) * HW_ + r2g] = roundtf(f3);
                cs[j][0] += f0 + f2;
                cs[j][1] += f1 + f3;
            }
        }
        #pragma unroll
        for (int j = 0; j < 8; j++)
            #pragma unroll
            for (int c = 0; c < 2; c++) {
                cs[j][c] += __shfl_xor_sync(0xFFFFFFFFu, cs[j][c], 4);
                cs[j][c] += __shfl_xor_sync(0xFFFFFFFFu, cs[j][c], 8);
                cs[j][c] += __shfl_xor_sync(0xFFFFFFFFu, cs[j][c], 16);
            }
        if (t4 == 0) {
            #pragma unroll
            for (int j = 0; j < 8; j++) {
                ps2[warpN0 + j * 8 + tm * 2][wid & 3]     = cs[j][0];
                ps2[warpN0 + j * 8 + tm * 2 + 1][wid & 3] = cs[j][1];
            }
        }
        __syncthreads();
        if (tid < 128) {
            g_ps[((size_t)b * HW_ + n0 + tid) * NT_ + ti] =
                ps2[tid][0] + ps2[tid][1] + ps2[tid][2] + ps2[tid][3];
        }
    }
}

// ---------------------------------------------------------------------------
// ctx partial: grid (2, 50, 8)
// ---------------------------------------------------------------------------
__global__ void __launch_bounds__(256) ctx_mma()
{
    const int b = blockIdx.z >> 2;
    const int sp = blockIdx.z & 3;
    const int n0 = blockIdx.x * 128;   // v-channel tile
    const int m0 = blockIdx.y * 128;   // pixel tile

    float acc[2][8][4] = {};
    mma_mainloop(g_sim + ((size_t)b * HW_ + m0) * HW_,
                 g_v + ((size_t)b * CV_ + n0) * HW_,
                 HW_, HW_, sp * KSPLIT, (sp + 1) * KSPLIT, acc);

    const int lane = threadIdx.x & 31;
    const int wid  = threadIdx.x >> 5;
    const int warpM0 = (wid & 3) * 32;
    const int warpN0 = (wid >> 2) * 64;
    const int t4 = lane >> 2;
    const int tm = lane & 3;

    float* Cp = g_ctxp + (size_t)(b * NSPLIT + sp) * HW_ * CV_;
    #pragma unroll
    for (int i = 0; i < 2; i++) {
        int r1 = m0 + warpM0 + i * 16 + t4;
        int r2 = r1 + 8;
        #pragma unroll
        for (int j = 0; j < 8; j++) {
            int cg = n0 + warpN0 + j * 8 + tm * 2;
            *(float2*)&Cp[(size_t)r1 * CV_ + cg] = make_float2(acc[i][j][0], acc[i][j][1]);
            *(float2*)&Cp[(size_t)r2 * CV_ + cg] = make_float2(acc[i][j][2], acc[i][j][3]);
        }
    }
}

// ---------------------------------------------------------------------------
// out: grid (50, 4, 2)
// ---------------------------------------------------------------------------
__global__ void __launch_bounds__(256) out_mma(
    const float* __restrict__ bW, float* __restrict__ out)
{
    const int b = blockIdx.z;
    const int n0 = blockIdx.x * 128;
    const int m0 = blockIdx.y * 128;

    float acc[2][8][4] = {};
    mma_mainloop(g_wr + 2 * 131072 + (size_t)m0 * CV_,
                 g_ctx + ((size_t)b * HW_ + n0) * CV_,
                 CV_, CV_, 0, CV_, acc);

    const int lane = threadIdx.x & 31;
    const int wid  = threadIdx.x >> 5;
    const int warpM0 = (wid & 3) * 32;
    const int warpN0 = (wid >> 2) * 64;
    const int t4 = lane >> 2;
    const int tm = lane & 3;

    float* O = out + (size_t)b * CO_ * HW_;
    #pragma unroll
    for (int i = 0; i < 2; i++) {
        int r1 = m0 + warpM0 + i * 16 + t4;
        int r2 = r1 + 8;
        float b1 = bW[r1], b2 = bW[r2];
        #pragma unroll
        for (int j = 0; j < 8; j++) {
            int cg = n0 + warpN0 + j * 8 + tm * 2;
            *(float2*)&O[(size_t)r1 * HW_ + cg] =
                make_float2(acc[i][j][0] + b1, acc[i][j][1] + b1);
            *(float2*)&O[(size_t)r2 * HW_ + cg] =
                make_float2(acc[i][j][2] + b2, acc[i][j][3] + b2);
        }
    }
}

// ---------------------------------------------------------------------------
// Small kernels
// ---------------------------------------------------------------------------
__global__ void __launch_bounds__(256) norm_kernel()
{
    const int w = threadIdx.x >> 5;
    const int lane = threadIdx.x & 31;
    const int row = blockIdx.x * 8 + w;
    const float* p = g_kt + (size_t)row * CK_ + lane * 8;
    float4 a = *(const float4*)p;
    float4 b = *(const float4*)(p + 4);
    float s = a.x*a.x + a.y*a.y + a.z*a.z + a.w*a.w
            + b.x*b.x + b.y*b.y + b.z*b.z + b.w*b.w;
    #pragma unroll
    for (int d = 16; d > 0; d >>= 1) s += __shfl_xor_sync(0xFFFFFFFFu, s, d);
    if (lane == 0) g_rn[row] = s;
}

__global__ void __launch_bounds__(256) gmax_kernel()
{
    const int b = blockIdx.x;
    const int tid = threadIdx.x;
    __shared__ float red[256];
    float m = 0.f;
    for (int i = tid; i < HW_; i += 256) m = fmaxf(m, g_rn[(size_t)b * HW_ + i]);
    red[tid] = m;
    __syncthreads();
    for (int s = 128; s > 0; s >>= 1) {
        if (tid < s) red[tid] = fmaxf(red[tid], red[tid + s]);
        __syncthreads();
    }
    if (tid == 0) g_gsq[b] = red[0];
}

__global__ void __launch_bounds__(256) rowinv_kernel()
{
    const int r = blockIdx.x * 256 + threadIdx.x;
    const float* p = g_ps + (size_t)r * NT_;
    float s = 0.f;
    #pragma unroll
    for (int j = 0; j < NT_; j++) s += p[j];
    g_inv[r] = 1.f / s;
}

__global__ void __launch_bounds__(256) reduce_ctx()
{
    const size_t f = (size_t)blockIdx.x * 256 + threadIdx.x;
    const size_t per_b = (size_t)HW_ * CV_;
    const size_t g = f * 4;
    const size_t b = g / per_b;
    const size_t e = g % per_b;
    const size_t n = e / CV_;
    const float inv = g_inv[b * HW_ + n];
    const float4 a = *(const float4*)&g_ctxp[(b * NSPLIT + 0) * per_b + e];
    const float4 c = *(const float4*)&g_ctxp[(b * NSPLIT + 1) * per_b + e];
    const float4 d = *(const float4*)&g_ctxp[(b * NSPLIT + 2) * per_b + e];
    const float4 h = *(const float4*)&g_ctxp[(b * NSPLIT + 3) * per_b + e];
    *(float4*)&g_ctx[b * per_b + e] = make_float4(
        roundtf((a.x + c.x + d.x + h.x) * inv),
        roundtf((a.y + c.y + d.y + h.y) * inv),
        roundtf((a.z + c.z + d.z + h.z) * inv),
        roundtf((a.w + c.w + d.w + h.w) * inv));
}

// ---------------------------------------------------------------------------
// Launch
// ---------------------------------------------------------------------------
extern "C" void kernel_launch(void* const* d_in, const int* in_sizes, int n_in,
                              void* d_out, int out_size)
{
    const float* x     = (const float*)d_in[0];
    const float* wk    = (const float*)d_in[1];
    const float* bk    = (const float*)d_in[2];
    const float* gamma = (const float*)d_in[3];
    const float* beta  = (const float*)d_in[4];
    const float* rmean = (const float*)d_in[5];
    const float* rvar  = (const float*)d_in[6];
    const float* wv    = (const float*)d_in[7];
    const float* bv    = (const float*)d_in[8];
    const float* wW    = (const float*)d_in[9];
    const float* bW    = (const float*)d_in[10];
    float* out = (float*)d_out;

    cudaFuncSetAttribute(kv_mma,  cudaFuncAttributeMaxDynamicSharedMemorySize, SMEM_DYN);
    cudaFuncSetAttribute(sim_sym, cudaFuncAttributeMaxDynamicSharedMemorySize, SMEM_DYN);
    cudaFuncSetAttribute(ctx_mma, cudaFuncAttributeMaxDynamicSharedMemorySize, SMEM_DYN);
    cudaFuncSetAttribute(out_mma, cudaFuncAttributeMaxDynamicSharedMemorySize, SMEM_DYN);

    dim3 blk(256);
    round_w<<<dim3(1536, 1, 1), blk>>>(wk, wv, wW);
    transpose_x<<<dim3(200, 16, 2), dim3(32, 8)>>>(x);
    kv_mma<<<dim3(50, 2, 4), blk, SMEM_DYN>>>(bk, gamma, beta, rmean, rvar, bv);
    norm_kernel<<<dim3(1600, 1, 1), blk>>>();
    gmax_kernel<<<dim3(2, 1, 1), blk>>>();
    sim_sym<<<dim3(1275, 1, 2), blk, SMEM_DYN>>>();
    rowinv_kernel<<<dim3(50, 1, 1), blk>>>();
    ctx_mma<<<dim3(2, 50, 2 * NSPLIT), blk, SMEM_DYN>>>();
    reduce_ctx<<<dim3(3200, 1, 1), blk>>>();
    out_mma<<<dim3(50, 4, 2), blk, SMEM_DYN>>>(bW, out);
}

// round 8
// speedup vs baseline: 6.3782x; 1.8556x over previous
#include <cuda_runtime.h>
#include <cuda_fp16.h>
#include <math.h>
#include <stdint.h>

#define BN_EPS 1e-5f

// Problem constants
#define B_   2
#define C_   512
#define HW_  6400
#define CK_  256
#define CV_  256
#define CO_  512
#define NSPLIT 4
#define KSPLIT (HW_ / NSPLIT)   // 1600
#define NT_  50                 // 6400 / 128 tiles per dim

#define NSTAGE 3
#define KCH   32                          // k-halfs per chunk
#define SROW  40                          // halfs per smem row (32 + 8 pad)
#define STAGE_H (2 * 128 * SROW)          // halfs per stage (A+B)
#define SMEM_DYN (NSTAGE * STAGE_H * 2)   // 61440 bytes

// ---------------------------------------------------------------------------
// Scratch (device globals)
// ---------------------------------------------------------------------------
__device__ __align__(16) __half g_xt [(size_t)B_ * HW_ * C_];   // x^T: [b][n][c]
__device__ __align__(16) __half g_wr [3 * 131072];              // wk | wv | wW (half)
__device__ __align__(16) __half g_kt [(size_t)B_ * HW_ * CK_];  // K^T: [pixel][channel]
__device__ __align__(16) __half g_v  [(size_t)B_ * CV_ * HW_];  // V: [vchan][pixel]
__device__ __align__(16) __half g_sim[(size_t)B_ * HW_ * HW_];  // exp(S - u_row)
__device__ __align__(16) __half g_ctx[(size_t)B_ * HW_ * CV_];  // ctx^T: [n][v] normalized
__device__ float g_ctxp[(size_t)B_ * NSPLIT * HW_ * CV_];       // ctx partials (fp32)
__device__ float g_rn  [(size_t)B_ * HW_];                      // ||k_r||^2 (of stored half K)
__device__ float g_gsq [B_];                                    // max_r ||k_r||^2
__device__ float g_ps  [(size_t)B_ * HW_ * NT_];                // row-sum partials
__device__ float g_inv [(size_t)B_ * HW_];                      // 1/rowsum

// ---------------------------------------------------------------------------
// Helpers
// ---------------------------------------------------------------------------
__device__ __forceinline__ void mma_f16(float* c, const uint32_t* a, const uint32_t* b) {
    asm volatile(
        "mma.sync.aligned.m16n8k16.row.col.f32.f16.f16.f32 "
        "{%0,%1,%2,%3}, {%4,%5,%6,%7}, {%8,%9}, {%0,%1,%2,%3};"
        : "+f"(c[0]), "+f"(c[1]), "+f"(c[2]), "+f"(c[3])
        : "r"(a[0]), "r"(a[1]), "r"(a[2]), "r"(a[3]), "r"(b[0]), "r"(b[1]));
}

__device__ __forceinline__ void cp16(uint32_t saddr, const void* g) {
    asm volatile("cp.async.cg.shared.global [%0], [%1], 16;" :: "r"(saddr), "l"(g));
}
__device__ __forceinline__ void cp_commit() {
    asm volatile("cp.async.commit_group;");
}
template<int N> __device__ __forceinline__ void cp_wait() {
    asm volatile("cp.async.wait_group %0;" :: "n"(N));
}

// ---------------------------------------------------------------------------
// Pipelined FP16 mainloop: acc += sum_{k in [kb,ke)} A[m][k]*B[n][k]
// A, B pre-offset to the tile's first row. 128x128 tile, 8 warps.
// ---------------------------------------------------------------------------
__device__ __forceinline__ void mma_mainloop_h(
    const __half* __restrict__ A, const __half* __restrict__ B,
    int lda, int ldb, int kb, int ke, float acc[2][8][4])
{
    extern __shared__ __half smh[];
    const int tid  = threadIdx.x;
    const int lane = tid & 31;
    const int wid  = tid >> 5;
    const int warpM0 = (wid & 3) * 32;
    const int warpN0 = (wid >> 2) * 64;
    const int t4 = lane >> 2;
    const int tm = lane & 3;

    const int lr   = tid >> 1;
    const int hseg = (tid & 1) * 16;

    const __half* Ar = A + (size_t)lr * lda + kb + hseg;
    const __half* Br = B + (size_t)lr * ldb + kb + hseg;

    const int ktiles = (ke - kb) / KCH;

#define ISSUE_TILE(stage, kof) do {                                           \
        __half* As_ = smh + (stage) * STAGE_H;                                \
        __half* Bs_ = As_ + 128 * SROW;                                       \
        uint32_t sa_ = (uint32_t)__cvta_generic_to_shared(&As_[lr*SROW+hseg]);\
        uint32_t sb_ = (uint32_t)__cvta_generic_to_shared(&Bs_[lr*SROW+hseg]);\
        cp16(sa_ +  0, Ar + (kof));     cp16(sb_ +  0, Br + (kof));           \
        cp16(sa_ + 16, Ar + (kof) + 8); cp16(sb_ + 16, Br + (kof) + 8);       \
    } while (0)

    ISSUE_TILE(0, 0);
    cp_commit();
    if (ktiles > 1) ISSUE_TILE(1, KCH);
    cp_commit();

    for (int t = 0; t < ktiles; t++) {
        const int cur = t % NSTAGE;
        if (t + 2 < ktiles) ISSUE_TILE((t + 2) % NSTAGE, (t + 2) * KCH);
        cp_commit();
        cp_wait<2>();
        __syncthreads();

        const __half* As = smh + cur * STAGE_H;
        const __half* Bs = As + 128 * SROW;

        #pragma unroll
        for (int s = 0; s < 2; s++) {
            uint32_t a[2][4], b[8][2];
            #pragma unroll
            for (int i = 0; i < 2; i++) {
                int base = (warpM0 + i * 16 + t4) * SROW + s * 16 + tm * 2;
                a[i][0] = *(const uint32_t*)&As[base];
                a[i][1] = *(const uint32_t*)&As[base + 8 * SROW];
                a[i][2] = *(const uint32_t*)&As[base + 8];
                a[i][3] = *(const uint32_t*)&As[base + 8 * SROW + 8];
            }
            #pragma unroll
            for (int j = 0; j < 8; j++) {
                int bb = (warpN0 + j * 8 + t4) * SROW + s * 16 + tm * 2;
                b[j][0] = *(const uint32_t*)&Bs[bb];
                b[j][1] = *(const uint32_t*)&Bs[bb + 8];
            }
            #pragma unroll
            for (int i = 0; i < 2; i++)
                #pragma unroll
                for (int j = 0; j < 8; j++)
                    mma_f16(acc[i][j], a[i], b[j]);
        }
        __syncthreads();
    }
#undef ISSUE_TILE
}

// ---------------------------------------------------------------------------
// Transpose + halve x: [b][c][n] -> g_xt [b][n][c].  grid (200,16,2), 32x8
// ---------------------------------------------------------------------------
__global__ void __launch_bounds__(256) transpose_x(const float* __restrict__ x)
{
    __shared__ float t[32][33];
    const int n0 = blockIdx.x * 32;
    const int c0 = blockIdx.y * 32;
    const int b  = blockIdx.z;
    const int tx = threadIdx.x, ty = threadIdx.y;

    #pragma unroll
    for (int j = 0; j < 4; j++) {
        int c = c0 + ty + j * 8;
        t[ty + j * 8][tx] = x[((size_t)b * C_ + c) * HW_ + n0 + tx];
    }
    __syncthreads();
    #pragma unroll
    for (int j = 0; j < 4; j++) {
        int n = n0 + ty + j * 8;
        g_xt[((size_t)b * HW_ + n) * C_ + c0 + tx] = __float2half_rn(t[tx][ty + j * 8]);
    }
}

// Halve weight matrices.  grid (1536), 256 thr
__global__ void __launch_bounds__(256) round_w(
    const float* __restrict__ wk, const float* __restrict__ wv,
    const float* __restrict__ wW)
{
    const int i = blockIdx.x * 256 + threadIdx.x;
    const float* src = (i < 131072) ? (wk + i)
                     : (i < 262144) ? (wv + i - 131072)
                                    : (wW + i - 262144);
    g_wr[i] = __float2half_rn(*src);
}

// ---------------------------------------------------------------------------
// kv via mma.  grid (50, 2, 4)  z = b*2 + isV
// ---------------------------------------------------------------------------
__global__ void __launch_bounds__(256) kv_mma(
    const float* __restrict__ bk,
    const float* __restrict__ gamma, const float* __restrict__ beta,
    const float* __restrict__ rmean, const float* __restrict__ rvar,
    const float* __restrict__ bv)
{
    const int n0 = blockIdx.x * 128;
    const int m0 = blockIdx.y * 128;
    const int b  = blockIdx.z >> 1;
    const int isV = blockIdx.z & 1;

    const __half* A = g_wr + (size_t)isV * 131072 + (size_t)m0 * C_;
    const __half* B = g_xt + ((size_t)b * HW_ + n0) * C_;

    float acc[2][8][4] = {};
    mma_mainloop_h(A, B, C_, C_, 0, C_, acc);

    const int lane = threadIdx.x & 31;
    const int wid  = threadIdx.x >> 5;
    const int warpM0 = (wid & 3) * 32;
    const int warpN0 = (wid >> 2) * 64;
    const int t4 = lane >> 2;
    const int tm = lane & 3;

    if (isV) {
        __half* V = g_v + (size_t)b * CV_ * HW_;
        #pragma unroll
        for (int i = 0; i < 2; i++) {
            int r1 = m0 + warpM0 + i * 16 + t4;
            int r2 = r1 + 8;
            float b1 = bv[r1], b2 = bv[r2];
            #pragma unroll
            for (int j = 0; j < 8; j++) {
                int cg = n0 + warpN0 + j * 8 + tm * 2;
                *(__half2*)&V[(size_t)r1 * HW_ + cg] =
                    __floats2half2_rn(acc[i][j][0] + b1, acc[i][j][1] + b1);
                *(__half2*)&V[(size_t)r2 * HW_ + cg] =
                    __floats2half2_rn(acc[i][j][2] + b2, acc[i][j][3] + b2);
            }
        }
    } else {
        __half* kt = g_kt + (size_t)b * HW_ * CK_;
        #pragma unroll
        for (int i = 0; i < 2; i++) {
            int r1 = m0 + warpM0 + i * 16 + t4;
            int r2 = r1 + 8;
            float bb1 = bk[r1], bb2 = bk[r2];
            float sc1 = gamma[r1] / sqrtf(rvar[r1] + BN_EPS);
            float sc2 = gamma[r2] / sqrtf(rvar[r2] + BN_EPS);
            float mu1 = rmean[r1], mu2 = rmean[r2];
            float be1 = beta[r1],  be2 = beta[r2];
            #pragma unroll
            for (int j = 0; j < 8; j++) {
                int cg = n0 + warpN0 + j * 8 + tm * 2;
                float t0 = fmaxf((acc[i][j][0] + bb1 - mu1) * sc1 + be1, 0.f);
                float t1 = fmaxf((acc[i][j][1] + bb1 - mu1) * sc1 + be1, 0.f);
                float t2 = fmaxf((acc[i][j][2] + bb2 - mu2) * sc2 + be2, 0.f);
                float t3 = fmaxf((acc[i][j][3] + bb2 - mu2) * sc2 + be2, 0.f);
                kt[(size_t)cg * CK_ + r1]       = __float2half_rn(t0);
                kt[(size_t)(cg + 1) * CK_ + r1] = __float2half_rn(t1);
                kt[(size_t)cg * CK_ + r2]       = __float2half_rn(t2);
                kt[(size_t)(cg + 1) * CK_ + r2] = __float2half_rn(t3);
            }
        }
    }
}

// ---------------------------------------------------------------------------
// Symmetric sim: fused exp + partial sums, mirror staged via smem.
// grid (1275, 1, 2), 256 threads.
// ---------------------------------------------------------------------------
__global__ void __launch_bounds__(256) sim_sym()
{
    int rem = blockIdx.x, ti = 0;
    while (rem >= NT_ - ti) { rem -= NT_ - ti; ti++; }
    const int tj = ti + rem;
    const int b  = blockIdx.z;
    const int m0 = ti * 128, n0 = tj * 128;

    const __half* Kt = g_kt + (size_t)b * HW_ * CK_;

    __shared__ float ps1[128][2];
    __shared__ float ps2[128][4];
    extern __shared__ __half smh[];

    float acc[2][8][4] = {};
    mma_mainloop_h(Kt + (size_t)m0 * CK_, Kt + (size_t)n0 * CK_,
                   CK_, CK_, 0, CK_, acc);

    const int tid  = threadIdx.x;
    const int lane = tid & 31;
    const int wid  = tid >> 5;
    const int warpM0 = (wid & 3) * 32;
    const int warpN0 = (wid >> 2) * 64;
    const int t4 = lane >> 2;
    const int tm = lane & 3;

    __half* S = g_sim + (size_t)b * HW_ * HW_;
    const float* rn = g_rn + (size_t)b * HW_;
    const float Gsq = g_gsq[b];
    const float SC = 0.0625f;

    // primary tile: rounded-half store + row-sum partials (of rounded values)
    float rs[2][2] = {};
    #pragma unroll
    for (int i = 0; i < 2; i++) {
        const int rl1 = warpM0 + i * 16 + t4;
        const int rl2 = rl1 + 8;
        const float u1 = sqrtf(rn[m0 + rl1] * Gsq) * SC;
        const float u2 = sqrtf(rn[m0 + rl2] * Gsq) * SC;
        #pragma unroll
        for (int j = 0; j < 8; j++) {
            const int cg = n0 + warpN0 + j * 8 + tm * 2;
            __half2 h1 = __floats2half2_rn(__expf(acc[i][j][0] * SC - u1),
                                           __expf(acc[i][j][1] * SC - u1));
            __half2 h2 = __floats2half2_rn(__expf(acc[i][j][2] * SC - u2),
                                           __expf(acc[i][j][3] * SC - u2));
            float2 f1 = __half22float2(h1);
            float2 f2 = __half22float2(h2);
            rs[i][0] += f1.x + f1.y;
            rs[i][1] += f2.x + f2.y;
            *(__half2*)&S[(size_t)(m0 + rl1) * HW_ + cg] = h1;
            *(__half2*)&S[(size_t)(m0 + rl2) * HW_ + cg] = h2;
        }
    }
    #pragma unroll
    for (int i = 0; i < 2; i++)
        #pragma unroll
        for (int r = 0; r < 2; r++) {
            rs[i][r] += __shfl_xor_sync(0xFFFFFFFFu, rs[i][r], 1);
            rs[i][r] += __shfl_xor_sync(0xFFFFFFFFu, rs[i][r], 2);
        }
    if (tm == 0) {
        #pragma unroll
        for (int i = 0; i < 2; i++) {
            ps1[warpM0 + i * 16 + t4][warpN0 >> 6]     = rs[i][0];
            ps1[warpM0 + i * 16 + t4 + 8][warpN0 >> 6] = rs[i][1];
        }
    }
    __syncthreads();
    if (tid < 128) {
        g_ps[((size_t)b * HW_ + m0 + tid) * NT_ + tj] = ps1[tid][0] + ps1[tid][1];
    }

    // mirror tile: exp with column's own bound; stage transposed in smem
    if (ti != tj) {
        cp_wait<0>();
        __syncthreads();          // smh (pipeline buffers) now free for reuse
        float cs[8][2] = {};
        #pragma unroll
        for (int j = 0; j < 8; j++) {
            const int cl = warpN0 + j * 8 + tm * 2;
            const float uc0 = sqrtf(rn[n0 + cl] * Gsq) * SC;
            const float uc1 = sqrtf(rn[n0 + cl + 1] * Gsq) * SC;
            #pragma unroll
            for (int i = 0; i < 2; i++) {
                const int r1 = warpM0 + i * 16 + t4;
                const int r2 = r1 + 8;
                __half h0 = __float2half_rn(__expf(acc[i][j][0] * SC - uc0));
                __half h1 = __float2half_rn(__expf(acc[i][j][1] * SC - uc1));
                __half h2 = __float2half_rn(__expf(acc[i][j][2] * SC - uc0));
                __half h3 = __float2half_rn(__expf(acc[i][j][3] * SC - uc1));
                smh[cl * 136 + r1]       = h0;
                smh[(cl + 1) * 136 + r1] = h1;
                smh[cl * 136 + r2]       = h2;
                smh[(cl + 1) * 136 + r2] = h3;
                cs[j][0] += __half2float(h0) + __half2float(h2);
                cs[j][1] += __half2float(h1) + __half2float(h3);
            }
        }
        #pragma unroll
        for (int j = 0; j < 8; j++)
            #pragma unroll
            for (int c = 0; c < 2; c++) {
                cs[j][c] += __shfl_xor_sync(0xFFFFFFFFu, cs[j][c], 4);
                cs[j][c] += __shfl_xor_sync(0xFFFFFFFFu, cs[j][c], 8);
                cs[j][c] += __shfl_xor_sync(0xFFFFFFFFu, cs[j][c], 16);
            }
        if (t4 == 0) {
            #pragma unroll
            for (int j = 0; j < 8; j++) {
                ps2[warpN0 + j * 8 + tm * 2][wid & 3]     = cs[j][0];
                ps2[warpN0 + j * 8 + tm * 2 + 1][wid & 3] = cs[j][1];
            }
        }
        __syncthreads();
        if (tid < 128) {
            g_ps[((size_t)b * HW_ + n0 + tid) * NT_ + ti] =
                ps2[tid][0] + ps2[tid][1] + ps2[tid][2] + ps2[tid][3];
        }
        // coalesced flush of mirror tile: rows of 128 halfs
        #pragma unroll
        for (int it = 0; it < 8; it++) {
            int row = (tid >> 4) + it * 16;     // 0..127 (mirror row = n0+row)
            int c8  = tid & 15;
            uint4 v = *(const uint4*)&smh[row * 136 + c8 * 8];
            *(uint4*)&S[(size_t)(n0 + row) * HW_ + m0 + c8 * 8] = v;
        }
    }
}

// ---------------------------------------------------------------------------
// ctx partial: grid (2, 50, 8)
// ---------------------------------------------------------------------------
__global__ void __launch_bounds__(256) ctx_mma()
{
    const int b = blockIdx.z >> 2;
    const int sp = blockIdx.z & 3;
    const int n0 = blockIdx.x * 128;   // v-channel tile
    const int m0 = blockIdx.y * 128;   // pixel tile

    float acc[2][8][4] = {};
    mma_mainloop_h(g_sim + ((size_t)b * HW_ + m0) * HW_,
                   g_v + ((size_t)b * CV_ + n0) * HW_,
                   HW_, HW_, sp * KSPLIT, (sp + 1) * KSPLIT, acc);

    const int lane = threadIdx.x & 31;
    const int wid  = threadIdx.x >> 5;
    const int warpM0 = (wid & 3) * 32;
    const int warpN0 = (wid >> 2) * 64;
    const int t4 = lane >> 2;
    const int tm = lane & 3;

    float* Cp = g_ctxp + (size_t)(b * NSPLIT + sp) * HW_ * CV_;
    #pragma unroll
    for (int i = 0; i < 2; i++) {
        int r1 = m0 + warpM0 + i * 16 + t4;
        int r2 = r1 + 8;
        #pragma unroll
        for (int j = 0; j < 8; j++) {
            int cg = n0 + warpN0 + j * 8 + tm * 2;
            *(float2*)&Cp[(size_t)r1 * CV_ + cg] = make_float2(acc[i][j][0], acc[i][j][1]);
            *(float2*)&Cp[(size_t)r2 * CV_ + cg] = make_float2(acc[i][j][2], acc[i][j][3]);
        }
    }
}

// ---------------------------------------------------------------------------
// out: grid (50, 4, 2)
// ---------------------------------------------------------------------------
__global__ void __launch_bounds__(256) out_mma(
    const float* __restrict__ bW, float* __restrict__ out)
{
    const int b = blockIdx.z;
    const int n0 = blockIdx.x * 128;
    const int m0 = blockIdx.y * 128;

    float acc[2][8][4] = {};
    mma_mainloop_h(g_wr + 2 * 131072 + (size_t)m0 * CV_,
                   g_ctx + ((size_t)b * HW_ + n0) * CV_,
                   CV_, CV_, 0, CV_, acc);

    const int lane = threadIdx.x & 31;
    const int wid  = threadIdx.x >> 5;
    const int warpM0 = (wid & 3) * 32;
    const int warpN0 = (wid >> 2) * 64;
    const int t4 = lane >> 2;
    const int tm = lane & 3;

    float* O = out + (size_t)b * CO_ * HW_;
    #pragma unroll
    for (int i = 0; i < 2; i++) {
        int r1 = m0 + warpM0 + i * 16 + t4;
        int r2 = r1 + 8;
        float b1 = bW[r1], b2 = bW[r2];
        #pragma unroll
        for (int j = 0; j < 8; j++) {
            int cg = n0 + warpN0 + j * 8 + tm * 2;
            *(float2*)&O[(size_t)r1 * HW_ + cg] =
                make_float2(acc[i][j][0] + b1, acc[i][j][1] + b1);
            *(float2*)&O[(size_t)r2 * HW_ + cg] =
                make_float2(acc[i][j][2] + b2, acc[i][j][3] + b2);
        }
    }
}

// ---------------------------------------------------------------------------
// Small kernels
// ---------------------------------------------------------------------------
__global__ void __launch_bounds__(256) norm_kernel()
{
    const int w = threadIdx.x >> 5;
    const int lane = threadIdx.x & 31;
    const int row = blockIdx.x * 8 + w;
    const __half* p = g_kt + (size_t)row * CK_ + lane * 8;
    float s = 0.f;
    #pragma unroll
    for (int i = 0; i < 4; i++) {
        float2 f = __half22float2(*(const __half2*)(p + i * 2));
        s += f.x * f.x + f.y * f.y;
    }
    #pragma unroll
    for (int d = 16; d > 0; d >>= 1) s += __shfl_xor_sync(0xFFFFFFFFu, s, d);
    if (lane == 0) g_rn[row] = s;
}

__global__ void __launch_bounds__(256) gmax_kernel()
{
    const int b = blockIdx.x;
    const int tid = threadIdx.x;
    __shared__ float red[256];
    float m = 0.f;
    for (int i = tid; i < HW_; i += 256) m = fmaxf(m, g_rn[(size_t)b * HW_ + i]);
    red[tid] = m;
    __syncthreads();
    for (int s = 128; s > 0; s >>= 1) {
        if (tid < s) red[tid] = fmaxf(red[tid], red[tid + s]);
        __syncthreads();
    }
    if (tid == 0) g_gsq[b] = red[0];
}

__global__ void __launch_bounds__(256) rowinv_kernel()
{
    const int r = blockIdx.x * 256 + threadIdx.x;
    const float* p = g_ps + (size_t)r * NT_;
    float s = 0.f;
    #pragma unroll
    for (int j = 0; j < NT_; j++) s += p[j];
    g_inv[r] = 1.f / s;
}

__global__ void __launch_bounds__(256) reduce_ctx()
{
    const size_t f = (size_t)blockIdx.x * 256 + threadIdx.x;
    const size_t per_b = (size_t)HW_ * CV_;
    const size_t g = f * 4;
    const size_t b = g / per_b;
    const size_t e = g % per_b;
    const size_t n = e / CV_;
    const float inv = g_inv[b * HW_ + n];
    const float4 a = *(const float4*)&g_ctxp[(b * NSPLIT + 0) * per_b + e];
    const float4 c = *(const float4*)&g_ctxp[(b * NSPLIT + 1) * per_b + e];
    const float4 d = *(const float4*)&g_ctxp[(b * NSPLIT + 2) * per_b + e];
    const float4 h = *(const float4*)&g_ctxp[(b * NSPLIT + 3) * per_b + e];
    __half2* dst = (__half2*)&g_ctx[b * per_b + e];
    dst[0] = __floats2half2_rn((a.x + c.x + d.x + h.x) * inv,
                               (a.y + c.y + d.y + h.y) * inv);
    dst[1] = __floats2half2_rn((a.z + c.z + d.z + h.z) * inv,
                               (a.w + c.w + d.w + h.w) * inv);
}

// ---------------------------------------------------------------------------
// Launch
// ---------------------------------------------------------------------------
extern "C" void kernel_launch(void* const* d_in, const int* in_sizes, int n_in,
                              void* d_out, int out_size)
{
    const float* x     = (const float*)d_in[0];
    const float* wk    = (const float*)d_in[1];
    const float* bk    = (const float*)d_in[2];
    const float* gamma = (const float*)d_in[3];
    const float* beta  = (const float*)d_in[4];
    const float* rmean = (const float*)d_in[5];
    const float* rvar  = (const float*)d_in[6];
    const float* wv    = (const float*)d_in[7];
    const float* bv    = (const float*)d_in[8];
    const float* wW    = (const float*)d_in[9];
    const float* bW    = (const float*)d_in[10];
    float* out = (float*)d_out;

    cudaFuncSetAttribute(kv_mma,  cudaFuncAttributeMaxDynamicSharedMemorySize, SMEM_DYN);
    cudaFuncSetAttribute(sim_sym, cudaFuncAttributeMaxDynamicSharedMemorySize, SMEM_DYN);
    cudaFuncSetAttribute(ctx_mma, cudaFuncAttributeMaxDynamicSharedMemorySize, SMEM_DYN);
    cudaFuncSetAttribute(out_mma, cudaFuncAttributeMaxDynamicSharedMemorySize, SMEM_DYN);

    dim3 blk(256);
    round_w<<<dim3(1536, 1, 1), blk>>>(wk, wv, wW);
    transpose_x<<<dim3(200, 16, 2), dim3(32, 8)>>>(x);
    kv_mma<<<dim3(50, 2, 4), blk, SMEM_DYN>>>(bk, gamma, beta, rmean, rvar, bv);
    norm_kernel<<<dim3(1600, 1, 1), blk>>>();
    gmax_kernel<<<dim3(2, 1, 1), blk>>>();
    sim_sym<<<dim3(1275, 1, 2), blk, SMEM_DYN>>>();
    rowinv_kernel<<<dim3(50, 1, 1), blk>>>();
    ctx_mma<<<dim3(2, 50, 2 * NSPLIT), blk, SMEM_DYN>>>();
    reduce_ctx<<<dim3(3200, 1, 1), blk>>>();
    out_mma<<<dim3(50, 4, 2), blk, SMEM_DYN>>>(bW, out);
}

// round 9
// speedup vs baseline: 7.4535x; 1.1686x over previous
#include <cuda_runtime.h>
#include <cuda_fp16.h>
#include <math.h>
#include <stdint.h>

#define BN_EPS 1e-5f

// Problem constants
#define B_   2
#define C_   512
#define HW_  6400
#define CK_  256
#define CV_  256
#define CO_  512
#define NSPLIT 4
#define KSPLIT (HW_ / NSPLIT)   // 1600
#define NT_  50                 // 6400 / 128 tiles per dim

#define NSTAGE 4
#define KCH   32                          // k-halfs per chunk
#define SROW  40                          // halfs per smem row (32 + 8 pad)
#define STAGE_H (2 * 128 * SROW)          // halfs per stage (A+B)
#define SMEM_DYN (NSTAGE * STAGE_H * 2)   // 81920 bytes

// ---------------------------------------------------------------------------
// Scratch (device globals)
// ---------------------------------------------------------------------------
__device__ __align__(16) __half g_xt [(size_t)B_ * HW_ * C_];   // x^T: [b][n][c]
__device__ __align__(16) __half g_wr [3 * 131072];              // wk | wv | wW (half)
__device__ __align__(16) __half g_kt [(size_t)B_ * HW_ * CK_];  // K^T: [pixel][channel]
__device__ __align__(16) __half g_v  [(size_t)B_ * CV_ * HW_];  // V: [vchan][pixel]
__device__ __align__(16) __half g_sim[(size_t)B_ * HW_ * HW_];  // exp(S - u_row)
__device__ __align__(16) __half g_ctx[(size_t)B_ * HW_ * CV_];  // ctx^T: [n][v] normalized
__device__ float g_ctxp[(size_t)B_ * NSPLIT * HW_ * CV_];       // ctx partials (fp32)
__device__ float g_rn  [(size_t)B_ * HW_];                      // ||k_r||^2 (stored-half K)
__device__ float g_gsq [B_];                                    // max_r ||k_r||^2
__device__ float g_ps  [(size_t)B_ * HW_ * NT_];                // row-sum partials
__device__ float g_inv [(size_t)B_ * HW_];                      // 1/rowsum

// ---------------------------------------------------------------------------
// Helpers
// ---------------------------------------------------------------------------
__device__ __forceinline__ void mma_f16(float* c, const uint32_t* a, const uint32_t* b) {
    asm volatile(
        "mma.sync.aligned.m16n8k16.row.col.f32.f16.f16.f32 "
        "{%0,%1,%2,%3}, {%4,%5,%6,%7}, {%8,%9}, {%0,%1,%2,%3};"
        : "+f"(c[0]), "+f"(c[1]), "+f"(c[2]), "+f"(c[3])
        : "r"(a[0]), "r"(a[1]), "r"(a[2]), "r"(a[3]), "r"(b[0]), "r"(b[1]));
}

__device__ __forceinline__ void ldm4(uint32_t& r0, uint32_t& r1, uint32_t& r2,
                                     uint32_t& r3, uint32_t addr) {
    asm volatile("ldmatrix.sync.aligned.m8n8.x4.shared.b16 {%0,%1,%2,%3}, [%4];"
                 : "=r"(r0), "=r"(r1), "=r"(r2), "=r"(r3) : "r"(addr));
}

__device__ __forceinline__ void cp16(uint32_t saddr, const void* g) {
    asm volatile("cp.async.cg.shared.global [%0], [%1], 16;" :: "r"(saddr), "l"(g));
}
__device__ __forceinline__ void cp_commit() {
    asm volatile("cp.async.commit_group;");
}
template<int N> __device__ __forceinline__ void cp_wait() {
    asm volatile("cp.async.wait_group %0;" :: "n"(N));
}

// ---------------------------------------------------------------------------
// Pipelined FP16 mainloop: acc += sum_{k in [kb,ke)} A[m][k]*B[n][k]
// 128x128 tile, 8 warps, 4-stage cp.async, ldmatrix fragment loads.
// Requires (ke-kb)/KCH >= 3.
// ---------------------------------------------------------------------------
__device__ __forceinline__ void mma_mainloop_h(
    const __half* __restrict__ A, const __half* __restrict__ B,
    int lda, int ldb, int kb, int ke, float acc[2][8][4])
{
    extern __shared__ __half smh[];
    const int tid  = threadIdx.x;
    const int lane = tid & 31;
    const int wid  = tid >> 5;
    const int warpM0 = (wid & 3) * 32;
    const int warpN0 = (wid >> 2) * 64;

    const int lr   = tid >> 1;
    const int hseg = (tid & 1) * 16;

    const __half* Ar = A + (size_t)lr * lda + kb + hseg;
    const __half* Br = B + (size_t)lr * ldb + kb + hseg;

    const uint32_t sbase = (uint32_t)__cvta_generic_to_shared(smh);

    // per-lane ldmatrix byte offsets within a stage
    uint32_t a_off[2][2], b_off[2][4];
    {
        const int ra = warpM0 + (lane & 15);
        const int ca = (lane >> 4) * 8;
        #pragma unroll
        for (int i = 0; i < 2; i++)
            #pragma unroll
            for (int s = 0; s < 2; s++)
                a_off[i][s] = (uint32_t)(((ra + i * 16) * SROW + s * 16 + ca) * 2);
        const int jj = lane >> 4;             // extra j within the x4
        const int cb = ((lane >> 3) & 1) * 8;
        #pragma unroll
        for (int jp = 0; jp < 4; jp++)
            #pragma unroll
            for (int s = 0; s < 2; s++)
                b_off[s][jp] = (uint32_t)((128 * SROW +
                    (warpN0 + (jp * 2 + jj) * 8 + (lane & 7)) * SROW + s * 16 + cb) * 2);
    }

    const int ktiles = (ke - kb) / KCH;

#define ISSUE_TILE(stage, kof) do {                                  \
        uint32_t so_ = sbase + (stage) * (STAGE_H * 2);              \
        uint32_t sa_ = so_ + (lr * SROW + hseg) * 2;                 \
        uint32_t sb_ = sa_ + 128 * SROW * 2;                         \
        cp16(sa_,      Ar + (kof));                                  \
        cp16(sa_ + 16, Ar + (kof) + 8);                              \
        cp16(sb_,      Br + (kof));                                  \
        cp16(sb_ + 16, Br + (kof) + 8);                              \
    } while (0)

    ISSUE_TILE(0, 0);       cp_commit();
    ISSUE_TILE(1, KCH);     cp_commit();
    ISSUE_TILE(2, 2 * KCH); cp_commit();

    for (int t = 0; t < ktiles; t++) {
        cp_wait<2>();
        __syncthreads();
        if (t + 3 < ktiles) ISSUE_TILE((t + 3) & 3, (t + 3) * KCH);
        cp_commit();

        const uint32_t so = sbase + (t & 3) * (STAGE_H * 2);
        #pragma unroll
        for (int s = 0; s < 2; s++) {
            uint32_t a[2][4], b[8][2];
            ldm4(a[0][0], a[0][1], a[0][2], a[0][3], so + a_off[0][s]);
            ldm4(a[1][0], a[1][1], a[1][2], a[1][3], so + a_off[1][s]);
            ldm4(b[0][0], b[0][1], b[1][0], b[1][1], so + b_off[s][0]);
            ldm4(b[2][0], b[2][1], b[3][0], b[3][1], so + b_off[s][1]);
            ldm4(b[4][0], b[4][1], b[5][0], b[5][1], so + b_off[s][2]);
            ldm4(b[6][0], b[6][1], b[7][0], b[7][1], so + b_off[s][3]);
            #pragma unroll
            for (int i = 0; i < 2; i++)
                #pragma unroll
                for (int j = 0; j < 8; j++)
                    mma_f16(acc[i][j], a[i], b[j]);
        }
    }
#undef ISSUE_TILE
}

// ---------------------------------------------------------------------------
// Transpose + halve x: [b][c][n] -> g_xt [b][n][c].  grid (200,16,2), 32x8
// ---------------------------------------------------------------------------
__global__ void __launch_bounds__(256) transpose_x(const float* __restrict__ x)
{
    __shared__ float t[32][33];
    const int n0 = blockIdx.x * 32;
    const int c0 = blockIdx.y * 32;
    const int b  = blockIdx.z;
    const int tx = threadIdx.x, ty = threadIdx.y;

    #pragma unroll
    for (int j = 0; j < 4; j++) {
        int c = c0 + ty + j * 8;
        t[ty + j * 8][tx] = x[((size_t)b * C_ + c) * HW_ + n0 + tx];
    }
    __syncthreads();
    #pragma unroll
    for (int j = 0; j < 4; j++) {
        int n = n0 + ty + j * 8;
        g_xt[((size_t)b * HW_ + n) * C_ + c0 + tx] = __float2half_rn(t[tx][ty + j * 8]);
    }
}

// Halve weight matrices.  grid (1536), 256 thr
__global__ void __launch_bounds__(256) round_w(
    const float* __restrict__ wk, const float* __restrict__ wv,
    const float* __restrict__ wW)
{
    const int i = blockIdx.x * 256 + threadIdx.x;
    const float* src = (i < 131072) ? (wk + i)
                     : (i < 262144) ? (wv + i - 131072)
                                    : (wW + i - 262144);
    g_wr[i] = __float2half_rn(*src);
}

// ---------------------------------------------------------------------------
// kv via mma.  grid (50, 2, 4)  z = b*2 + isV
// ---------------------------------------------------------------------------
__global__ void __launch_bounds__(256, 2) kv_mma(
    const float* __restrict__ bk,
    const float* __restrict__ gamma, const float* __restrict__ beta,
    const float* __restrict__ rmean, const float* __restrict__ rvar,
    const float* __restrict__ bv)
{
    const int n0 = blockIdx.x * 128;
    const int m0 = blockIdx.y * 128;
    const int b  = blockIdx.z >> 1;
    const int isV = blockIdx.z & 1;

    const __half* A = g_wr + (size_t)isV * 131072 + (size_t)m0 * C_;
    const __half* B = g_xt + ((size_t)b * HW_ + n0) * C_;

    float acc[2][8][4] = {};
    mma_mainloop_h(A, B, C_, C_, 0, C_, acc);

    const int lane = threadIdx.x & 31;
    const int wid  = threadIdx.x >> 5;
    const int warpM0 = (wid & 3) * 32;
    const int warpN0 = (wid >> 2) * 64;
    const int t4 = lane >> 2;
    const int tm = lane & 3;

    if (isV) {
        __half* V = g_v + (size_t)b * CV_ * HW_;
        #pragma unroll
        for (int i = 0; i < 2; i++) {
            int r1 = m0 + warpM0 + i * 16 + t4;
            int r2 = r1 + 8;
            float b1 = bv[r1], b2 = bv[r2];
            #pragma unroll
            for (int j = 0; j < 8; j++) {
                int cg = n0 + warpN0 + j * 8 + tm * 2;
                *(__half2*)&V[(size_t)r1 * HW_ + cg] =
                    __floats2half2_rn(acc[i][j][0] + b1, acc[i][j][1] + b1);
                *(__half2*)&V[(size_t)r2 * HW_ + cg] =
                    __floats2half2_rn(acc[i][j][2] + b2, acc[i][j][3] + b2);
            }
        }
    } else {
        __half* kt = g_kt + (size_t)b * HW_ * CK_;
        #pragma unroll
        for (int i = 0; i < 2; i++) {
            int r1 = m0 + warpM0 + i * 16 + t4;
            int r2 = r1 + 8;
            float bb1 = bk[r1], bb2 = bk[r2];
            float sc1 = gamma[r1] / sqrtf(rvar[r1] + BN_EPS);
            float sc2 = gamma[r2] / sqrtf(rvar[r2] + BN_EPS);
            float mu1 = rmean[r1], mu2 = rmean[r2];
            float be1 = beta[r1],  be2 = beta[r2];
            #pragma unroll
            for (int j = 0; j < 8; j++) {
                int cg = n0 + warpN0 + j * 8 + tm * 2;
                float t0 = fmaxf((acc[i][j][0] + bb1 - mu1) * sc1 + be1, 0.f);
                float t1 = fmaxf((acc[i][j][1] + bb1 - mu1) * sc1 + be1, 0.f);
                float t2 = fmaxf((acc[i][j][2] + bb2 - mu2) * sc2 + be2, 0.f);
                float t3 = fmaxf((acc[i][j][3] + bb2 - mu2) * sc2 + be2, 0.f);
                kt[(size_t)cg * CK_ + r1]       = __float2half_rn(t0);
                kt[(size_t)(cg + 1) * CK_ + r1] = __float2half_rn(t1);
                kt[(size_t)cg * CK_ + r2]       = __float2half_rn(t2);
                kt[(size_t)(cg + 1) * CK_ + r2] = __float2half_rn(t3);
            }
        }
    }
}

// ---------------------------------------------------------------------------
// Symmetric sim: fused exp + partial sums, mirror staged via smem.
// grid (1275, 1, 2), 256 threads.
// ---------------------------------------------------------------------------
__global__ void __launch_bounds__(256, 2) sim_sym()
{
    int rem = blockIdx.x, ti = 0;
    while (rem >= NT_ - ti) { rem -= NT_ - ti; ti++; }
    const int tj = ti + rem;
    const int b  = blockIdx.z;
    const int m0 = ti * 128, n0 = tj * 128;

    const __half* Kt = g_kt + (size_t)b * HW_ * CK_;

    __shared__ float ps1[128][2];
    __shared__ float ps2[128][4];
    extern __shared__ __half smh[];

    float acc[2][8][4] = {};
    mma_mainloop_h(Kt + (size_t)m0 * CK_, Kt + (size_t)n0 * CK_,
                   CK_, CK_, 0, CK_, acc);

    const int tid  = threadIdx.x;
    const int lane = tid & 31;
    const int wid  = tid >> 5;
    const int warpM0 = (wid & 3) * 32;
    const int warpN0 = (wid >> 2) * 64;
    const int t4 = lane >> 2;
    const int tm = lane & 3;

    __half* S = g_sim + (size_t)b * HW_ * HW_;
    const float* rn = g_rn + (size_t)b * HW_;
    const float Gsq = g_gsq[b];
    const float SC = 0.0625f;

    // primary tile: rounded-half store + row-sum partials (of rounded values)
    float rs[2][2] = {};
    #pragma unroll
    for (int i = 0; i < 2; i++) {
        const int rl1 = warpM0 + i * 16 + t4;
        const int rl2 = rl1 + 8;
        const float u1 = sqrtf(rn[m0 + rl1] * Gsq) * SC;
        const float u2 = sqrtf(rn[m0 + rl2] * Gsq) * SC;
        #pragma unroll
        for (int j = 0; j < 8; j++) {
            const int cg = n0 + warpN0 + j * 8 + tm * 2;
            __half2 h1 = __floats2half2_rn(__expf(acc[i][j][0] * SC - u1),
                                           __expf(acc[i][j][1] * SC - u1));
            __half2 h2 = __floats2half2_rn(__expf(acc[i][j][2] * SC - u2),
                                           __expf(acc[i][j][3] * SC - u2));
            float2 f1 = __half22float2(h1);
            float2 f2 = __half22float2(h2);
            rs[i][0] += f1.x + f1.y;
            rs[i][1] += f2.x + f2.y;
            *(__half2*)&S[(size_t)(m0 + rl1) * HW_ + cg] = h1;
            *(__half2*)&S[(size_t)(m0 + rl2) * HW_ + cg] = h2;
        }
    }
    #pragma unroll
    for (int i = 0; i < 2; i++)
        #pragma unroll
        for (int r = 0; r < 2; r++) {
            rs[i][r] += __shfl_xor_sync(0xFFFFFFFFu, rs[i][r], 1);
            rs[i][r] += __shfl_xor_sync(0xFFFFFFFFu, rs[i][r], 2);
        }
    if (tm == 0) {
        #pragma unroll
        for (int i = 0; i < 2; i++) {
            ps1[warpM0 + i * 16 + t4][warpN0 >> 6]     = rs[i][0];
            ps1[warpM0 + i * 16 + t4 + 8][warpN0 >> 6] = rs[i][1];
        }
    }
    __syncthreads();
    if (tid < 128) {
        g_ps[((size_t)b * HW_ + m0 + tid) * NT_ + tj] = ps1[tid][0] + ps1[tid][1];
    }

    // mirror tile: exp with column's own bound; stage transposed in smem
    if (ti != tj) {
        cp_wait<0>();
        __syncthreads();          // pipeline buffers now free for reuse
        float cs[8][2] = {};
        #pragma unroll
        for (int j = 0; j < 8; j++) {
            const int cl = warpN0 + j * 8 + tm * 2;
            const float uc0 = sqrtf(rn[n0 + cl] * Gsq) * SC;
            const float uc1 = sqrtf(rn[n0 + cl + 1] * Gsq) * SC;
            #pragma unroll
            for (int i = 0; i < 2; i++) {
                const int r1 = warpM0 + i * 16 + t4;
                const int r2 = r1 + 8;
                __half h0 = __float2half_rn(__expf(acc[i][j][0] * SC - uc0));
                __half h1 = __float2half_rn(__expf(acc[i][j][1] * SC - uc1));
                __half h2 = __float2half_rn(__expf(acc[i][j][2] * SC - uc0));
                __half h3 = __float2half_rn(__expf(acc[i][j][3] * SC - uc1));
                smh[cl * 136 + r1]       = h0;
                smh[(cl + 1) * 136 + r1] = h1;
                smh[cl * 136 + r2]       = h2;
                smh[(cl + 1) * 136 + r2] = h3;
                cs[j][0] += __half2float(h0) + __half2float(h2);
                cs[j][1] += __half2float(h1) + __half2float(h3);
            }
        }
        #pragma unroll
        for (int j = 0; j < 8; j++)
            #pragma unroll
            for (int c = 0; c < 2; c++) {
                cs[j][c] += __shfl_xor_sync(0xFFFFFFFFu, cs[j][c], 4);
                cs[j][c] += __shfl_xor_sync(0xFFFFFFFFu, cs[j][c], 8);
                cs[j][c] += __shfl_xor_sync(0xFFFFFFFFu, cs[j][c], 16);
            }
        if (t4 == 0) {
            #pragma unroll
            for (int j = 0; j < 8; j++) {
                ps2[warpN0 + j * 8 + tm * 2][wid & 3]     = cs[j][0];
                ps2[warpN0 + j * 8 + tm * 2 + 1][wid & 3] = cs[j][1];
            }
        }
        __syncthreads();
        if (tid < 128) {
            g_ps[((size_t)b * HW_ + n0 + tid) * NT_ + ti] =
                ps2[tid][0] + ps2[tid][1] + ps2[tid][2] + ps2[tid][3];
        }
        // coalesced flush of mirror tile
        #pragma unroll
        for (int it = 0; it < 8; it++) {
            int row = (tid >> 4) + it * 16;
            int c8  = tid & 15;
            uint4 v = *(const uint4*)&smh[row * 136 + c8 * 8];
            *(uint4*)&S[(size_t)(n0 + row) * HW_ + m0 + c8 * 8] = v;
        }
    }
}

// ---------------------------------------------------------------------------
// ctx partial: grid (2, 50, 8)
// ---------------------------------------------------------------------------
__global__ void __launch_bounds__(256, 2) ctx_mma()
{
    const int b = blockIdx.z >> 2;
    const int sp = blockIdx.z & 3;
    const int n0 = blockIdx.x * 128;   // v-channel tile
    const int m0 = blockIdx.y * 128;   // pixel tile

    float acc[2][8][4] = {};
    mma_mainloop_h(g_sim + ((size_t)b * HW_ + m0) * HW_,
                   g_v + ((size_t)b * CV_ + n0) * HW_,
                   HW_, HW_, sp * KSPLIT, (sp + 1) * KSPLIT, acc);

    const int lane = threadIdx.x & 31;
    const int wid  = threadIdx.x >> 5;
    const int warpM0 = (wid & 3) * 32;
    const int warpN0 = (wid >> 2) * 64;
    const int t4 = lane >> 2;
    const int tm = lane & 3;

    float* Cp = g_ctxp + (size_t)(b * NSPLIT + sp) * HW_ * CV_;
    #pragma unroll
    for (int i = 0; i < 2; i++) {
        int r1 = m0 + warpM0 + i * 16 + t4;
        int r2 = r1 + 8;
        #pragma unroll
        for (int j = 0; j < 8; j++) {
            int cg = n0 + warpN0 + j * 8 + tm * 2;
            *(float2*)&Cp[(size_t)r1 * CV_ + cg] = make_float2(acc[i][j][0], acc[i][j][1]);
            *(float2*)&Cp[(size_t)r2 * CV_ + cg] = make_float2(acc[i][j][2], acc[i][j][3]);
        }
    }
}

// ---------------------------------------------------------------------------
// out: grid (50, 4, 2)
// ---------------------------------------------------------------------------
__global__ void __launch_bounds__(256, 2) out_mma(
    const float* __restrict__ bW, float* __restrict__ out)
{
    const int b = blockIdx.z;
    const int n0 = blockIdx.x * 128;
    const int m0 = blockIdx.y * 128;

    float acc[2][8][4] = {};
    mma_mainloop_h(g_wr + 2 * 131072 + (size_t)m0 * CV_,
                   g_ctx + ((size_t)b * HW_ + n0) * CV_,
                   CV_, CV_, 0, CV_, acc);

    const int lane = threadIdx.x & 31;
    const int wid  = threadIdx.x >> 5;
    const int warpM0 = (wid & 3) * 32;
    const int warpN0 = (wid >> 2) * 64;
    const int t4 = lane >> 2;
    const int tm = lane & 3;

    float* O = out + (size_t)b * CO_ * HW_;
    #pragma unroll
    for (int i = 0; i < 2; i++) {
        int r1 = m0 + warpM0 + i * 16 + t4;
        int r2 = r1 + 8;
        float b1 = bW[r1], b2 = bW[r2];
        #pragma unroll
        for (int j = 0; j < 8; j++) {
            int cg = n0 + warpN0 + j * 8 + tm * 2;
            *(float2*)&O[(size_t)r1 * HW_ + cg] =
                make_float2(acc[i][j][0] + b1, acc[i][j][1] + b1);
            *(float2*)&O[(size_t)r2 * HW_ + cg] =
                make_float2(acc[i][j][2] + b2, acc[i][j][3] + b2);
        }
    }
}

// ---------------------------------------------------------------------------
// Small kernels
// ---------------------------------------------------------------------------
__global__ void __launch_bounds__(256) norm_kernel()
{
    const int w = threadIdx.x >> 5;
    const int lane = threadIdx.x & 31;
    const int row = blockIdx.x * 8 + w;
    const __half* p = g_kt + (size_t)row * CK_ + lane * 8;
    float s = 0.f;
    #pragma unroll
    for (int i = 0; i < 4; i++) {
        float2 f = __half22float2(*(const __half2*)(p + i * 2));
        s += f.x * f.x + f.y * f.y;
    }
    #pragma unroll
    for (int d = 16; d > 0; d >>= 1) s += __shfl_xor_sync(0xFFFFFFFFu, s, d);
    if (lane == 0) g_rn[row] = s;
}

__global__ void __launch_bounds__(256) gmax_kernel()
{
    const int b = blockIdx.x;
    const int tid = threadIdx.x;
    __shared__ float red[256];
    float m = 0.f;
    for (int i = tid; i < HW_; i += 256) m = fmaxf(m, g_rn[(size_t)b * HW_ + i]);
    red[tid] = m;
    __syncthreads();
    for (int s = 128; s > 0; s >>= 1) {
        if (tid < s) red[tid] = fmaxf(red[tid], red[tid + s]);
        __syncthreads();
    }
    if (tid == 0) g_gsq[b] = red[0];
}

__global__ void __launch_bounds__(256) rowinv_kernel()
{
    const int r = blockIdx.x * 256 + threadIdx.x;
    const float* p = g_ps + (size_t)r * NT_;
    float s = 0.f;
    #pragma unroll
    for (int j = 0; j < NT_; j++) s += p[j];
    g_inv[r] = 1.f / s;
}

__global__ void __launch_bounds__(256) reduce_ctx()
{
    const size_t f = (size_t)blockIdx.x * 256 + threadIdx.x;
    const size_t per_b = (size_t)HW_ * CV_;
    const size_t g = f * 4;
    const size_t b = g / per_b;
    const size_t e = g % per_b;
    const size_t n = e / CV_;
    const float inv = g_inv[b * HW_ + n];
    const float4 a = *(const float4*)&g_ctxp[(b * NSPLIT + 0) * per_b + e];
    const float4 c = *(const float4*)&g_ctxp[(b * NSPLIT + 1) * per_b + e];
    const float4 d = *(const float4*)&g_ctxp[(b * NSPLIT + 2) * per_b + e];
    const float4 h = *(const float4*)&g_ctxp[(b * NSPLIT + 3) * per_b + e];
    __half2* dst = (__half2*)&g_ctx[b * per_b + e];
    dst[0] = __floats2half2_rn((a.x + c.x + d.x + h.x) * inv,
                               (a.y + c.y + d.y + h.y) * inv);
    dst[1] = __floats2half2_rn((a.z + c.z + d.z + h.z) * inv,
                               (a.w + c.w + d.w + h.w) * inv);
}

// ---------------------------------------------------------------------------
// Launch
// ---------------------------------------------------------------------------
extern "C" void kernel_launch(void* const* d_in, const int* in_sizes, int n_in,
                              void* d_out, int out_size)
{
    const float* x     = (const float*)d_in[0];
    const float* wk    = (const float*)d_in[1];
    const float* bk    = (const float*)d_in[2];
    const float* gamma = (const float*)d_in[3];
    const float* beta  = (const float*)d_in[4];
    const float* rmean = (const float*)d_in[5];
    const float* rvar  = (const float*)d_in[6];
    const float* wv    = (const float*)d_in[7];
    const float* bv    = (const float*)d_in[8];
    const float* wW    = (const float*)d_in[9];
    const float* bW    = (const float*)d_in[10];
    float* out = (float*)d_out;

    cudaFuncSetAttribute(kv_mma,  cudaFuncAttributeMaxDynamicSharedMemorySize, SMEM_DYN);
    cudaFuncSetAttribute(sim_sym, cudaFuncAttributeMaxDynamicSharedMemorySize, SMEM_DYN);
    cudaFuncSetAttribute(ctx_mma, cudaFuncAttributeMaxDynamicSharedMemorySize, SMEM_DYN);
    cudaFuncSetAttribute(out_mma, cudaFuncAttributeMaxDynamicSharedMemorySize, SMEM_DYN);

    dim3 blk(256);
    round_w<<<dim3(1536, 1, 1), blk>>>(wk, wv, wW);
    transpose_x<<<dim3(200, 16, 2), dim3(32, 8)>>>(x);
    kv_mma<<<dim3(50, 2, 4), blk, SMEM_DYN>>>(bk, gamma, beta, rmean, rvar, bv);
    norm_kernel<<<dim3(1600, 1, 1), blk>>>();
    gmax_kernel<<<dim3(2, 1, 1), blk>>>();
    sim_sym<<<dim3(1275, 1, 2), blk, SMEM_DYN>>>();
    rowinv_kernel<<<dim3(50, 1, 1), blk>>>();
    ctx_mma<<<dim3(2, 50, 2 * NSPLIT), blk, SMEM_DYN>>>();
    reduce_ctx<<<dim3(3200, 1, 1), blk>>>();
    out_mma<<<dim3(50, 4, 2), blk, SMEM_DYN>>>(bW, out);
}